// round 4
// baseline (speedup 1.0000x reference)
#include <cuda_runtime.h>
#include <math.h>
#include <stdint.h>

#define BATCH 512
#define LATENT 128

// ---------------- scratch (static device arrays; no runtime allocs) ----------
__device__ float g_lp[BATCH * 32];                 //   64 KB
__device__ float g_b0[BATCH * 128 * 8 * 8];        // 16.8 MB  [n][128][8][8]
__device__ float g_b1[BATCH * 128 * 16 * 16];      // 67 MB    [n][128][16][16]
__device__ float g_b2[BATCH * 64 * 32 * 32];       // 134 MB   [n][64][32][32]

// ---------------- tf32 helpers ----------------
__device__ __forceinline__ uint32_t tf32cvt(float f) {
    uint32_t r;
    asm("cvt.rna.tf32.f32 %0, %1;" : "=r"(r) : "f"(f));
    return r;
}
__device__ __forceinline__ void mma_tf32(float* d, const uint32_t* a, const uint32_t* b) {
    asm("mma.sync.aligned.m16n8k8.row.col.f32.tf32.tf32.f32 "
        "{%0,%1,%2,%3}, {%4,%5,%6,%7}, {%8,%9}, {%0,%1,%2,%3};"
        : "+f"(d[0]), "+f"(d[1]), "+f"(d[2]), "+f"(d[3])
        : "r"(a[0]), "r"(a[1]), "r"(a[2]), "r"(a[3]), "r"(b[0]), "r"(b[1]));
}

// ---------------- stage 1: gating + soft-tree leaf probabilities -------------
__global__ void leaf_kernel(const float* __restrict__ x,
                            const float* __restrict__ gw,
                            const float* __restrict__ gb,
                            float* __restrict__ lp) {
    int b = blockIdx.x;
    int lane = threadIdx.x;
    __shared__ float xs[LATENT];
    __shared__ float gs[32];
    for (int k = lane; k < LATENT; k += 32) xs[k] = x[b * LATENT + k];
    __syncthreads();
    if (lane < 31) {
        float acc = gb[lane];
#pragma unroll 8
        for (int k = 0; k < LATENT; k++) acc += xs[k] * gw[k * 31 + lane];
        gs[lane] = 1.0f / (1.0f + expf(-acc));
    }
    __syncthreads();
    float dens = 1.0f;
    int l = lane;
#pragma unroll
    for (int d = 1; d <= 5; d++) {
        int par  = l >> (6 - d);
        int gate = (1 << (d - 1)) - 1 + par;
        int bit  = (l >> (5 - d)) & 1;
        float gv = gs[gate];
        dens *= bit ? (1.0f - gv) : gv;
    }
    lp[b * 32 + l] = dens;
}

// ---------------- stage 2: out0[b][f] = sum_l lp[b][l] * z[f][l] -------------
__global__ void mix_kernel(const float* __restrict__ lp,
                           const float* __restrict__ z,
                           float* __restrict__ out0) {
    __shared__ float lps[8][32];
    int tid = threadIdx.x;
    int f = blockIdx.x * 256 + tid;
    int b0 = blockIdx.y * 8;
    lps[tid >> 5][tid & 31] = lp[b0 * 32 + tid];
    __syncthreads();
    float4 zr[8];
    const float4* zp = (const float4*)(z + (size_t)f * 32);
#pragma unroll
    for (int j = 0; j < 8; j++) zr[j] = zp[j];
#pragma unroll
    for (int bb = 0; bb < 8; bb++) {
        const float* lr = lps[bb];
        float acc = 0.0f;
#pragma unroll
        for (int j = 0; j < 8; j++) {
            float4 zv = zr[j];
            acc += zv.x * lr[4 * j] + zv.y * lr[4 * j + 1]
                 + zv.z * lr[4 * j + 2] + zv.w * lr[4 * j + 3];
        }
        out0[(size_t)(b0 + bb) * 8192 + f] = acc;
    }
}

// ---------------- conv transpose via tf32 mma.sync implicit GEMM -------------
// Per parity class (py,px): D[oc][pix] = sum_{ic,tap} A[oc][ic*4+tap] * B[ic*4+tap][pix]
// A[oc][k] = w[ic][oc][3-py-2*ra][3-px-2*rb],  B[k][(q,r)] = x[ic][q+py-1+ra][r+px-1+rb]
// (zero outside). M=COUT, N=HIN*HIN (class pixel grid), K=CIN*4.
// 256 threads / 8 warps. K-chunks of 16 staged in smem; B swizzled n ^ 8*(k&3).
template <int CIN, int HIN, int COUT, bool RELU>
__launch_bounds__(256)
__global__ void convt_mma_kernel(const float* __restrict__ in,
                                 const float* __restrict__ w,
                                 const float* __restrict__ bias,
                                 float* __restrict__ out) {
    constexpr int NPIX = HIN * HIN;       // N per class
    constexpr int HOUT = 2 * HIN;
    constexpr int KC   = 16;              // K chunk (4 input channels)
    constexpr int M    = COUT;
    constexpr int MT   = M / 16;          // m-tiles (4 or 8)
    constexpr int NGRP = 8 / MT;          // warp groups along N
    constexpr int NSUB = (NPIX / 8) / NGRP;  // n-subtiles per warp

    extern __shared__ uint32_t smu[];
    uint32_t* A_sm = smu;                 // [M][KC]
    uint32_t* B_sm = smu + M * KC;        // [KC][NPIX], swizzled

    const int cls = blockIdx.x;
    const int n_img = blockIdx.y;
    const int py = cls >> 1, px = cls & 1;
    const int tid = threadIdx.x;
    const int warp = tid >> 5, lane = tid & 31;
    const int m0 = (warp % MT) * 16;
    const int n0 = (warp / MT) * (NSUB * 8);
    const int lg = lane >> 2;             // group id 0..7
    const int lt = lane & 3;              // thread in group

    float d[NSUB][4];
#pragma unroll
    for (int s = 0; s < NSUB; s++)
#pragma unroll
        for (int j = 0; j < 4; j++) d[s][j] = 0.0f;

    const float* inb = in + (size_t)n_img * CIN * NPIX;

    for (int ic0 = 0; ic0 < CIN; ic0 += KC / 4) {
        __syncthreads();
        // ---- stage A chunk: A_sm[m][kk] ----
        for (int idx = tid; idx < KC * M; idx += 256) {
            int m  = idx % M;
            int kk = idx / M;
            int ic = ic0 + (kk >> 2);
            int tap = kk & 3;
            int ra = tap >> 1, rb = tap & 1;
            int ky = 3 - py - 2 * ra;
            int kx = 3 - px - 2 * rb;
            float v = w[((size_t)ic * COUT + m) * 16 + ky * 4 + kx];
            A_sm[m * KC + kk] = tf32cvt(v);
        }
        // ---- stage B chunk: B_sm[kk][n ^ 8*(kk&3)] ----
        for (int idx = tid; idx < KC * NPIX; idx += 256) {
            int n  = idx % NPIX;
            int kk = idx / NPIX;
            int q = n / HIN, r = n % HIN;
            int ic = ic0 + (kk >> 2);
            int tap = kk & 3;
            int ra = tap >> 1, rb = tap & 1;
            int row = q + py - 1 + ra;
            int col = r + px - 1 + rb;
            float v = 0.0f;
            if (row >= 0 && row < HIN && col >= 0 && col < HIN)
                v = inb[(size_t)ic * NPIX + row * HIN + col];
            B_sm[kk * NPIX + (n ^ (8 * tap))] = tf32cvt(v);
        }
        __syncthreads();

        // ---- mma over the 2 k-steps of this chunk ----
#pragma unroll
        for (int c = 0; c < KC / 8; c++) {
            uint32_t a[4];
            a[0] = A_sm[(m0 + lg) * KC + c * 8 + lt];
            a[1] = A_sm[(m0 + lg + 8) * KC + c * 8 + lt];
            a[2] = A_sm[(m0 + lg) * KC + c * 8 + lt + 4];
            a[3] = A_sm[(m0 + lg + 8) * KC + c * 8 + lt + 4];
#pragma unroll
            for (int s = 0; s < NSUB; s++) {
                int n = n0 + s * 8 + lg;
                int swn = n ^ (8 * lt);   // k&3 == lt for both b regs
                uint32_t b[2];
                b[0] = B_sm[(c * 8 + lt) * NPIX + swn];
                b[1] = B_sm[(c * 8 + lt + 4) * NPIX + swn];
                mma_tf32(d[s], a, b);
            }
        }
    }

    // ---- epilogue: bias (+ReLU), scatter to output pixel grid ----
    float* outb = out + (size_t)n_img * COUT * HOUT * HOUT;
    float bv0 = bias[m0 + lg];
    float bv1 = bias[m0 + lg + 8];
#pragma unroll
    for (int s = 0; s < NSUB; s++) {
        int nb = n0 + s * 8 + 2 * lt;
        int q = nb / HIN, r = nb % HIN;   // nb,nb+1 share q (8-aligned blocks)
        int oy = 2 * q + py;
        int ox0 = 2 * r + px;
#pragma unroll
        for (int half = 0; half < 2; half++) {
            int oc = m0 + lg + 8 * half;
            float v0 = d[s][2 * half]     + (half ? bv1 : bv0);
            float v1 = d[s][2 * half + 1] + (half ? bv1 : bv0);
            if (RELU) { v0 = fmaxf(v0, 0.0f); v1 = fmaxf(v1, 0.0f); }
            float* orow = outb + ((size_t)oc * HOUT + oy) * HOUT;
            orow[ox0]     = v0;
            orow[ox0 + 2] = v1;
        }
    }
}

// ---------------- scalar ConvTranspose2d (round-2 proven path, for conv3) ----
template <int CIN, int HIN, int COUT, int U, int T, int ICB, bool RELU>
__global__ void convt_kernel(const float* __restrict__ in,
                             const float* __restrict__ w,
                             const float* __restrict__ bias,
                             float* __restrict__ out) {
    constexpr int HOUT    = 2 * HIN;
    constexpr int NPIX    = HIN * HIN;
    constexpr int GPR     = HIN / T;
    constexpr int PGROUPS = NPIX / T;
    constexpr int OGROUPS = COUT / U;
    constexpr int THREADS = PGROUPS * OGROUPS;

    extern __shared__ float sm[];
    float* xs = sm;
    float* ws = sm + ICB * NPIX;

    const int n   = blockIdx.x;
    const int cls = blockIdx.y;
    const int py = cls >> 1, px = cls & 1;
    const int tid = threadIdx.x;
    const int p  = tid % PGROUPS;
    const int u0 = (tid / PGROUPS) * U;
    const int q  = p / GPR;
    const int r0 = (p % GPR) * T;

    const int row_base = q + py - 1;
    const int col_base = r0 + px - 1;
    bool rowok[2];
    int  rowix[2];
    rowok[0] = (row_base >= 0);       rowix[0] = rowok[0] ? row_base : 0;
    rowok[1] = (row_base + 1 < HIN);  rowix[1] = rowok[1] ? row_base + 1 : 0;
    bool colok[T + 1];
    int  colix[T + 1];
#pragma unroll
    for (int c = 0; c <= T; c++) {
        int cc = col_base + c;
        colok[c] = (cc >= 0 && cc < HIN);
        colix[c] = colok[c] ? cc : 0;
    }

    float acc[U][T];
#pragma unroll
    for (int uu = 0; uu < U; uu++)
#pragma unroll
        for (int t = 0; t < T; t++) acc[uu][t] = 0.0f;

    const float* inb = in + (size_t)n * CIN * NPIX;

    for (int ic0 = 0; ic0 < CIN; ic0 += ICB) {
        __syncthreads();
        for (int idx = tid; idx < ICB * NPIX; idx += THREADS)
            xs[idx] = inb[(size_t)ic0 * NPIX + idx];
        for (int idx = tid; idx < ICB * COUT * 4; idx += THREADS) {
            int i   = idx / (COUT * 4);
            int rem = idx - i * (COUT * 4);
            int oc  = rem >> 2;
            int t4  = rem & 3;
            int ra = t4 >> 1, rb = t4 & 1;
            int ky = 3 - py - 2 * ra;
            int kx = 3 - px - 2 * rb;
            ws[idx] = w[((size_t)(ic0 + i) * COUT + oc) * 16 + ky * 4 + kx];
        }
        __syncthreads();

        for (int i = 0; i < ICB; i++) {
            float xv[2][T + 1];
#pragma unroll
            for (int a = 0; a < 2; a++) {
                const float* xr = xs + (i * HIN + rowix[a]) * HIN;
#pragma unroll
                for (int c = 0; c <= T; c++) {
                    float v = xr[colix[c]];
                    xv[a][c] = (rowok[a] && colok[c]) ? v : 0.0f;
                }
            }
            const float* wsi = ws + (i * COUT + u0) * 4;
#pragma unroll
            for (int uu = 0; uu < U; uu++) {
                float w00 = wsi[uu * 4 + 0];
                float w01 = wsi[uu * 4 + 1];
                float w10 = wsi[uu * 4 + 2];
                float w11 = wsi[uu * 4 + 3];
#pragma unroll
                for (int t = 0; t < T; t++)
                    acc[uu][t] += xv[0][t] * w00 + xv[0][t + 1] * w01
                                + xv[1][t] * w10 + xv[1][t + 1] * w11;
            }
        }
    }

    const int oy = 2 * q + py;
    float* outb = out + (size_t)n * COUT * HOUT * HOUT;
#pragma unroll
    for (int uu = 0; uu < U; uu++) {
        int oc = u0 + uu;
        float bv = bias[oc];
        float* orow = outb + ((size_t)oc * HOUT + oy) * HOUT;
#pragma unroll
        for (int t = 0; t < T; t++) {
            int ox = 2 * (r0 + t) + px;
            float v = acc[uu][t] + bv;
            if (RELU) v = fmaxf(v, 0.0f);
            orow[ox] = v;
        }
    }
}

// ---------------- launch -----------------------------------------------------
extern "C" void kernel_launch(void* const* d_in, const int* in_sizes, int n_in,
                              void* d_out, int out_size) {
    const float* x  = (const float*)d_in[0];
    const float* gw = (const float*)d_in[1];
    const float* gb = (const float*)d_in[2];
    const float* z  = (const float*)d_in[3];
    const float* w1 = (const float*)d_in[4];
    const float* b1 = (const float*)d_in[5];
    const float* w2 = (const float*)d_in[6];
    const float* b2 = (const float*)d_in[7];
    const float* w3 = (const float*)d_in[8];
    const float* b3 = (const float*)d_in[9];
    float* out = (float*)d_out;

    float *lp, *bf0, *bf1, *bf2;
    cudaGetSymbolAddress((void**)&lp,  g_lp);
    cudaGetSymbolAddress((void**)&bf0, g_b0);
    cudaGetSymbolAddress((void**)&bf1, g_b1);
    cudaGetSymbolAddress((void**)&bf2, g_b2);

    leaf_kernel<<<BATCH, 32>>>(x, gw, gb, lp);
    mix_kernel<<<dim3(8192 / 256, BATCH / 8), 256>>>(lp, z, bf0);

    // conv1: 128 -> 128, 8x8 -> 16x16, ReLU.  tf32 mma.
    // smem = A 128*16*4 + B 16*64*4 = 8192 + 4096 = 12288 B
    convt_mma_kernel<128, 8, 128, true>
        <<<dim3(4, BATCH), 256, (128 * 16 + 16 * 64) * 4>>>(bf0, w1, b1, bf1);
    // conv2: 128 -> 64, 16x16 -> 32x32, ReLU.  tf32 mma.
    // smem = A 64*16*4 + B 16*256*4 = 4096 + 16384 = 20480 B
    convt_mma_kernel<128, 16, 64, true>
        <<<dim3(4, BATCH), 256, (64 * 16 + 16 * 256) * 4>>>(bf1, w2, b2, bf2);
    // conv3: 64 -> 3, 32x32 -> 64x64, no ReLU. scalar fp32 (6% of FLOPs).
    convt_kernel<64, 32, 3, 3, 4, 8, false>
        <<<dim3(BATCH, 4), 256, (8 * 1024 + 8 * 3 * 4) * sizeof(float)>>>(bf2, w3, b3, out);
}

// round 5
// speedup vs baseline: 2.6501x; 2.6501x over previous
#include <cuda_runtime.h>
#include <math.h>
#include <stdint.h>

#define BATCH 512
#define LATENT 128

// ---------------- scratch (static device arrays; no runtime allocs) ----------
__device__ float g_lp[BATCH * 32];                 //   64 KB
__device__ float g_b0[BATCH * 128 * 8 * 8];        // 16.8 MB  [n][128][8][8]
__device__ float g_b1[BATCH * 128 * 16 * 16];      // 67 MB
__device__ float g_b2[BATCH * 64 * 32 * 32];       // 134 MB
// pre-reordered tf32 weights: [cls][tap][ic][Mpad]
__device__ uint32_t g_wr1[4 * 4 * 128 * 136];      // conv1  (1.1 MB)
__device__ uint32_t g_wr2[4 * 4 * 128 * 72];       // conv2
__device__ uint32_t g_wr3[4 * 4 * 64 * 40];        // conv3

// ---------------- tf32 helpers ----------------
__device__ __forceinline__ uint32_t tf32cvt(float f) {
    uint32_t r;
    asm("cvt.rna.tf32.f32 %0, %1;" : "=r"(r) : "f"(f));
    return r;
}
__device__ __forceinline__ void mma_tf32(float* d, const uint32_t* a, const uint32_t* b) {
    asm("mma.sync.aligned.m16n8k8.row.col.f32.tf32.tf32.f32 "
        "{%0,%1,%2,%3}, {%4,%5,%6,%7}, {%8,%9}, {%0,%1,%2,%3};"
        : "+f"(d[0]), "+f"(d[1]), "+f"(d[2]), "+f"(d[3])
        : "r"(a[0]), "r"(a[1]), "r"(a[2]), "r"(a[3]), "r"(b[0]), "r"(b[1]));
}

// ---------------- stage 1: gating + soft-tree leaf probabilities -------------
__global__ void leaf_kernel(const float* __restrict__ x,
                            const float* __restrict__ gw,
                            const float* __restrict__ gb,
                            float* __restrict__ lp) {
    int b = blockIdx.x;
    int lane = threadIdx.x;
    __shared__ float xs[LATENT];
    __shared__ float gs[32];
    for (int k = lane; k < LATENT; k += 32) xs[k] = x[b * LATENT + k];
    __syncthreads();
    if (lane < 31) {
        float acc = gb[lane];
#pragma unroll 8
        for (int k = 0; k < LATENT; k++) acc += xs[k] * gw[k * 31 + lane];
        gs[lane] = 1.0f / (1.0f + expf(-acc));
    }
    __syncthreads();
    float dens = 1.0f;
    int l = lane;
#pragma unroll
    for (int d = 1; d <= 5; d++) {
        int par  = l >> (6 - d);
        int gate = (1 << (d - 1)) - 1 + par;
        int bit  = (l >> (5 - d)) & 1;
        float gv = gs[gate];
        dens *= bit ? (1.0f - gv) : gv;
    }
    lp[b * 32 + l] = dens;
}

// ---------------- stage 2: out0[b][f] = sum_l lp[b][l] * z[f][l] -------------
__global__ void mix_kernel(const float* __restrict__ lp,
                           const float* __restrict__ z,
                           float* __restrict__ out0) {
    __shared__ float lps[8][32];
    int tid = threadIdx.x;
    int f = blockIdx.x * 256 + tid;
    int b0 = blockIdx.y * 8;
    lps[tid >> 5][tid & 31] = lp[b0 * 32 + tid];
    __syncthreads();
    float4 zr[8];
    const float4* zp = (const float4*)(z + (size_t)f * 32);
#pragma unroll
    for (int j = 0; j < 8; j++) zr[j] = zp[j];
#pragma unroll
    for (int bb = 0; bb < 8; bb++) {
        const float* lr = lps[bb];
        float acc = 0.0f;
#pragma unroll
        for (int j = 0; j < 8; j++) {
            float4 zv = zr[j];
            acc += zv.x * lr[4 * j] + zv.y * lr[4 * j + 1]
                 + zv.z * lr[4 * j + 2] + zv.w * lr[4 * j + 3];
        }
        out0[(size_t)(b0 + bb) * 8192 + f] = acc;
    }
}

// ---------------- weight prep: wr[cls][tap][ic][MP] = tf32(w'), pad m>=COUT=0 -
template <int CIN, int COUT, int MP>
__global__ void prep_kernel(const float* __restrict__ w, uint32_t* __restrict__ wr) {
    int idx = blockIdx.x * 256 + threadIdx.x;
    if (idx >= 4 * 4 * CIN * MP) return;
    int m   = idx % MP;
    int t2  = idx / MP;
    int ic  = t2 % CIN;
    int t3  = t2 / CIN;
    int tap = t3 & 3;
    int cls = t3 >> 2;
    int py = cls >> 1, px = cls & 1;
    int ra = tap >> 1, rb = tap & 1;
    int ky = 3 - py - 2 * ra;
    int kx = 3 - px - 2 * rb;
    uint32_t v = 0;
    if (m < COUT)
        v = tf32cvt(w[((size_t)ic * COUT + m) * 16 + ky * 4 + kx]);
    wr[idx] = v;
}

// ---------------- ConvTranspose2d(k4,s2,p1) via tf32 mma, halo-padded B ------
// Per parity class: D[oc][pix] = sum_tap sum_ic A_tap[oc][ic] * X[ic][pix+shift(tap)]
// B = raw input staged in smem with zero halo; taps = 4 shifted base offsets.
template <int CIN, int HIN, int COUT, int MTILE, int ICB, int IMGB, int MP, bool RELU>
__launch_bounds__(256)
__global__ void convt_mma2(const float* __restrict__ in,
                           const uint32_t* __restrict__ wr,
                           const float* __restrict__ bias,
                           float* __restrict__ out) {
    constexpr int NPIX = HIN * HIN;
    constexpr int HOUT = 2 * HIN;
    constexpr int PW   = HIN + 2;
    constexpr int PP   = PW * PW;
    constexpr int CH   = ((PP - 9) / 32 + 1) * 32 + 8;   // channel stride, ==8 mod 32
    constexpr int NGRP = 8 / MTILE;
    constexpr int NTOT = IMGB * NPIX;
    constexpr int NSUB = NTOT / (8 * NGRP);
    constexpr int LOGH = (HIN == 8) ? 3 : (HIN == 16) ? 4 : 5;
    constexpr int KST  = ICB / 8;                        // k-steps per tap per chunk

    extern __shared__ uint32_t smu[];
    uint32_t* A_sm = smu;                    // [4][ICB][MP]
    uint32_t* B_sm = smu + 4 * ICB * MP;     // [IMGB][ICB][CH] padded images

    const int cls = blockIdx.x;
    const int img0 = blockIdx.y * IMGB;
    const int py = cls >> 1, px = cls & 1;
    const int tid = threadIdx.x;
    const int warp = tid >> 5, lane = tid & 31;
    const int lg = lane >> 2, lt = lane & 3;
    const int m0 = (warp % MTILE) * 16;
    const int n0 = (warp / MTILE) * (NSUB * 8);

    // zero halo regions (whole B once; interior overwritten every chunk)
    for (int i = tid; i < IMGB * ICB * CH; i += 256) B_sm[i] = 0;

    // per-tap shift offsets into padded image
    int toff[4];
#pragma unroll
    for (int t = 0; t < 4; t++)
        toff[t] = (py - 1 + (t >> 1)) * PW + (px - 1 + (t & 1));

    // per-subtile pixel base address (halo-shifted interior)
    int base[NSUB];
#pragma unroll
    for (int s = 0; s < NSUB; s++) {
        int n = n0 + s * 8 + lg;
        int im = n >> (2 * LOGH);          // n / NPIX
        int pix = n & (NPIX - 1);
        int q = pix >> LOGH, r = pix & (HIN - 1);
        base[s] = im * (ICB * CH) + (q + 1) * PW + (r + 1);
    }

    float d[NSUB][4];
#pragma unroll
    for (int s = 0; s < NSUB; s++)
#pragma unroll
        for (int j = 0; j < 4; j++) d[s][j] = 0.0f;

    const uint32_t* wrc = wr + (size_t)cls * 4 * CIN * MP;

    for (int ic0 = 0; ic0 < CIN; ic0 += ICB) {
        __syncthreads();
        // stage A chunk: contiguous copy per tap
        for (int idx = tid; idx < 4 * ICB * MP; idx += 256) {
            int t   = idx / (ICB * MP);
            int rem = idx - t * (ICB * MP);
            A_sm[idx] = wrc[(t * CIN + ic0) * MP + rem];
        }
        // stage B chunk: raw image interior, tf32-converted
        for (int idx = tid; idx < IMGB * ICB * NPIX; idx += 256) {
            int im  = idx / (ICB * NPIX);
            int rem = idx - im * (ICB * NPIX);
            int ic  = rem >> (2 * LOGH);
            int pix = rem & (NPIX - 1);
            int q = pix >> LOGH, r = pix & (HIN - 1);
            float v = in[((size_t)(img0 + im) * CIN + ic0 + ic) * NPIX + pix];
            B_sm[im * (ICB * CH) + ic * CH + (q + 1) * PW + (r + 1)] = tf32cvt(v);
        }
        __syncthreads();

#pragma unroll
        for (int t = 0; t < 4; t++) {
#pragma unroll
            for (int c = 0; c < KST; c++) {
                uint32_t a[4];
                const uint32_t* Ar = A_sm + (t * ICB + c * 8 + lt) * MP;
                a[0] = Ar[m0 + lg];
                a[1] = Ar[m0 + lg + 8];
                a[2] = Ar[4 * MP + m0 + lg];
                a[3] = Ar[4 * MP + m0 + lg + 8];
                const int kb = (c * 8 + lt) * CH + toff[t];
#pragma unroll
                for (int s = 0; s < NSUB; s++) {
                    uint32_t b[2];
                    b[0] = B_sm[kb + base[s]];
                    b[1] = B_sm[kb + 4 * CH + base[s]];
                    mma_tf32(d[s], a, b);
                }
            }
        }
    }

    // epilogue
#pragma unroll
    for (int s = 0; s < NSUB; s++) {
        int nb = n0 + s * 8 + 2 * lt;
        int im = nb >> (2 * LOGH);
        int pix = nb & (NPIX - 1);
        int q = pix >> LOGH, r = pix & (HIN - 1);
        int oy = 2 * q + py;
        int ox0 = 2 * r + px;
        float* outb = out + (size_t)(img0 + im) * COUT * HOUT * HOUT;
#pragma unroll
        for (int half = 0; half < 2; half++) {
            int oc = m0 + lg + 8 * half;
            if (oc < COUT) {
                float bv = bias[oc];
                float v0 = d[s][2 * half]     + bv;
                float v1 = d[s][2 * half + 1] + bv;
                if (RELU) { v0 = fmaxf(v0, 0.0f); v1 = fmaxf(v1, 0.0f); }
                float* orow = outb + ((size_t)oc * HOUT + oy) * HOUT;
                orow[ox0]     = v0;
                orow[ox0 + 2] = v1;
            }
        }
    }
}

// ---------------- launch -----------------------------------------------------
extern "C" void kernel_launch(void* const* d_in, const int* in_sizes, int n_in,
                              void* d_out, int out_size) {
    const float* x  = (const float*)d_in[0];
    const float* gw = (const float*)d_in[1];
    const float* gb = (const float*)d_in[2];
    const float* z  = (const float*)d_in[3];
    const float* w1 = (const float*)d_in[4];
    const float* b1 = (const float*)d_in[5];
    const float* w2 = (const float*)d_in[6];
    const float* b2 = (const float*)d_in[7];
    const float* w3 = (const float*)d_in[8];
    const float* b3 = (const float*)d_in[9];
    float* out = (float*)d_out;

    float *lp, *bf0, *bf1, *bf2;
    uint32_t *wr1, *wr2, *wr3;
    cudaGetSymbolAddress((void**)&lp,  g_lp);
    cudaGetSymbolAddress((void**)&bf0, g_b0);
    cudaGetSymbolAddress((void**)&bf1, g_b1);
    cudaGetSymbolAddress((void**)&bf2, g_b2);
    cudaGetSymbolAddress((void**)&wr1, g_wr1);
    cudaGetSymbolAddress((void**)&wr2, g_wr2);
    cudaGetSymbolAddress((void**)&wr3, g_wr3);

    leaf_kernel<<<BATCH, 32>>>(x, gw, gb, lp);
    mix_kernel<<<dim3(8192 / 256, BATCH / 8), 256>>>(lp, z, bf0);

    // weight prep (tiny)
    prep_kernel<128, 128, 136><<<(4 * 4 * 128 * 136 + 255) / 256, 256>>>(w1, wr1);
    prep_kernel<128, 64, 72><<<(4 * 4 * 128 * 72 + 255) / 256, 256>>>(w2, wr2);
    prep_kernel<64, 3, 40><<<(4 * 4 * 64 * 40 + 255) / 256, 256>>>(w3, wr3);

    // conv1: 128->128, 8x8 -> 16x16, ReLU.  MTILE=8, ICB=16, IMGB=2, MP=136
    // smem = A 4*16*136*4 + B 2*16*104*4 = 34816 + 13312 = 48128 B
    convt_mma2<128, 8, 128, 8, 16, 2, 136, true>
        <<<dim3(4, BATCH / 2), 256, 48128>>>(bf0, wr1, b1, bf1);
    // conv2: 128->64, 16x16 -> 32x32, ReLU. MTILE=4, ICB=16, IMGB=1, MP=72
    // smem = A 4*16*72*4 + B 16*328*4 = 18432 + 20992 = 39424 B
    convt_mma2<128, 16, 64, 4, 16, 1, 72, true>
        <<<dim3(4, BATCH), 256, 39424>>>(bf1, wr2, b2, bf2);
    // conv3: 64->3, 32x32 -> 64x64, no ReLU. MTILE=1, ICB=8, IMGB=1, MP=40
    // smem = A 4*8*40*4 + B 8*1160*4 = 5120 + 37120 = 42240 B
    convt_mma2<64, 32, 3, 1, 8, 1, 40, false>
        <<<dim3(4, BATCH), 256, 42240>>>(bf2, wr3, b3, out);
}

// round 6
// speedup vs baseline: 4.5442x; 1.7148x over previous
#include <cuda_runtime.h>
#include <math.h>
#include <stdint.h>

#define BATCH 512
#define LATENT 128

// ---------------- scratch (static device arrays; no runtime allocs) ----------
__device__ float g_lp[BATCH * 32];
__device__ float g_b0[BATCH * 128 * 8 * 8];        // tf32-rounded f32
__device__ float g_b1[BATCH * 128 * 16 * 16];      // tf32-rounded f32
__device__ float g_b2[BATCH * 64 * 32 * 32];       // tf32-rounded f32
// pre-reordered tf32 weights
__device__ uint32_t g_wr1[4 * 4 * 128 * 136];      // [cls][tap][ic][MP]
__device__ uint32_t g_wr2[4 * 4 * 128 * 72];
__device__ uint32_t g_wr3[4 * 4 * 64 * 8];         // [cls][tap][ic][8 oc]

// ---------------- tf32 helpers ----------------
__device__ __forceinline__ uint32_t tf32cvt(float f) {
    uint32_t r;
    asm("cvt.rna.tf32.f32 %0, %1;" : "=r"(r) : "f"(f));
    return r;
}
__device__ __forceinline__ float tf32round(float f) {
    return __uint_as_float(tf32cvt(f));
}
__device__ __forceinline__ void mma_tf32(float* d, const uint32_t* a, const uint32_t* b) {
    asm("mma.sync.aligned.m16n8k8.row.col.f32.tf32.tf32.f32 "
        "{%0,%1,%2,%3}, {%4,%5,%6,%7}, {%8,%9}, {%0,%1,%2,%3};"
        : "+f"(d[0]), "+f"(d[1]), "+f"(d[2]), "+f"(d[3])
        : "r"(a[0]), "r"(a[1]), "r"(a[2]), "r"(a[3]), "r"(b[0]), "r"(b[1]));
}

// ---------------- stage 1: gating + soft-tree leaf probabilities -------------
__global__ void leaf_kernel(const float* __restrict__ x,
                            const float* __restrict__ gw,
                            const float* __restrict__ gb,
                            float* __restrict__ lp) {
    int b = blockIdx.x;
    int lane = threadIdx.x;
    __shared__ float xs[LATENT];
    __shared__ float gs[32];
    for (int k = lane; k < LATENT; k += 32) xs[k] = x[b * LATENT + k];
    __syncthreads();
    if (lane < 31) {
        float acc = gb[lane];
#pragma unroll 8
        for (int k = 0; k < LATENT; k++) acc += xs[k] * gw[k * 31 + lane];
        gs[lane] = 1.0f / (1.0f + expf(-acc));
    }
    __syncthreads();
    float dens = 1.0f;
    int l = lane;
#pragma unroll
    for (int d = 1; d <= 5; d++) {
        int par  = l >> (6 - d);
        int gate = (1 << (d - 1)) - 1 + par;
        int bit  = (l >> (5 - d)) & 1;
        float gv = gs[gate];
        dens *= bit ? (1.0f - gv) : gv;
    }
    lp[b * 32 + l] = dens;
}

// ---------------- stage 2: mix (stores tf32-rounded values) ------------------
__global__ void mix_kernel(const float* __restrict__ lp,
                           const float* __restrict__ z,
                           float* __restrict__ out0) {
    __shared__ float lps[8][32];
    int tid = threadIdx.x;
    int f = blockIdx.x * 256 + tid;
    int b0 = blockIdx.y * 8;
    lps[tid >> 5][tid & 31] = lp[b0 * 32 + tid];
    __syncthreads();
    float4 zr[8];
    const float4* zp = (const float4*)(z + (size_t)f * 32);
#pragma unroll
    for (int j = 0; j < 8; j++) zr[j] = zp[j];
#pragma unroll
    for (int bb = 0; bb < 8; bb++) {
        const float* lr = lps[bb];
        float acc = 0.0f;
#pragma unroll
        for (int j = 0; j < 8; j++) {
            float4 zv = zr[j];
            acc += zv.x * lr[4 * j] + zv.y * lr[4 * j + 1]
                 + zv.z * lr[4 * j + 2] + zv.w * lr[4 * j + 3];
        }
        out0[(size_t)(b0 + bb) * 8192 + f] = tf32round(acc);
    }
}

// ---------------- weight prep (conv1/conv2): wr[cls][tap][ic][MP] ------------
template <int CIN, int COUT, int MP>
__global__ void prep_kernel(const float* __restrict__ w, uint32_t* __restrict__ wr) {
    int idx = blockIdx.x * 256 + threadIdx.x;
    if (idx >= 4 * 4 * CIN * MP) return;
    int m   = idx % MP;
    int t2  = idx / MP;
    int ic  = t2 % CIN;
    int t3  = t2 / CIN;
    int tap = t3 & 3;
    int cls = t3 >> 2;
    int py = cls >> 1, px = cls & 1;
    int ra = tap >> 1, rb = tap & 1;
    int ky = 3 - py - 2 * ra;
    int kx = 3 - px - 2 * rb;
    uint32_t v = 0;
    if (m < COUT)
        v = tf32cvt(w[((size_t)ic * COUT + m) * 16 + ky * 4 + kx]);
    wr[idx] = v;
}

// ---------------- weight prep (conv3): wr3[cls][tap][ic][8 oc] ---------------
__global__ void prep3_kernel(const float* __restrict__ w, uint32_t* __restrict__ wr) {
    int idx = blockIdx.x * 256 + threadIdx.x;
    if (idx >= 4 * 4 * 64 * 8) return;
    int oc  = idx & 7;
    int ic  = (idx >> 3) & 63;
    int tap = (idx >> 9) & 3;
    int cls = idx >> 11;
    int py = cls >> 1, px = cls & 1;
    int ra = tap >> 1, rb = tap & 1;
    int ky = 3 - py - 2 * ra;
    int kx = 3 - px - 2 * rb;
    uint32_t v = 0;
    if (oc < 3)
        v = tf32cvt(w[((size_t)ic * 3 + oc) * 16 + ky * 4 + kx]);
    wr[idx] = v;
}

// ---------------- conv1/conv2: tf32 mma, MT2=2 m-blocking --------------------
template <int CIN, int HIN, int COUT, int MGRP, int ICB, int IMGB, int MP, bool RELU>
__launch_bounds__(256, 2)
__global__ void convt_mma3(const float* __restrict__ in,
                           const uint32_t* __restrict__ wr,
                           const float* __restrict__ bias,
                           float* __restrict__ out) {
    constexpr int NPIX = HIN * HIN;
    constexpr int HOUT = 2 * HIN;
    constexpr int PW   = HIN + 2;
    constexpr int PP   = PW * PW;
    constexpr int CH   = ((PP - 9) / 32 + 1) * 32 + 8;   // channel stride ==8 mod 32
    constexpr int NGRP = 8 / MGRP;
    constexpr int NTOT = IMGB * NPIX;
    constexpr int NSUB = NTOT / (8 * NGRP);
    constexpr int LOGH = (HIN == 8) ? 3 : 4;
    constexpr int KST  = ICB / 8;

    extern __shared__ uint32_t smu[];
    uint32_t* A_sm = smu;                    // [4][ICB][MP]
    uint32_t* B_sm = smu + 4 * ICB * MP;     // [IMGB][ICB][CH]

    const int cls = blockIdx.x;
    const int img0 = blockIdx.y * IMGB;
    const int py = cls >> 1, px = cls & 1;
    const int tid = threadIdx.x;
    const int warp = tid >> 5, lane = tid & 31;
    const int lg = lane >> 2, lt = lane & 3;
    const int m0 = (warp % MGRP) * 32;
    const int n0 = (warp / MGRP) * (NSUB * 8);

    for (int i = tid; i < IMGB * ICB * CH; i += 256) B_sm[i] = 0;

    int toff[4];
#pragma unroll
    for (int t = 0; t < 4; t++)
        toff[t] = (py - 1 + (t >> 1)) * PW + (px - 1 + (t & 1));

    int base[NSUB];
#pragma unroll
    for (int s = 0; s < NSUB; s++) {
        int n = n0 + s * 8 + lg;
        int im = n >> (2 * LOGH);
        int pix = n & (NPIX - 1);
        int q = pix >> LOGH, r = pix & (HIN - 1);
        base[s] = im * (ICB * CH) + (q + 1) * PW + (r + 1);
    }

    float d[2][NSUB][4];
#pragma unroll
    for (int mm = 0; mm < 2; mm++)
#pragma unroll
        for (int s = 0; s < NSUB; s++)
#pragma unroll
            for (int j = 0; j < 4; j++) d[mm][s][j] = 0.0f;

    const uint32_t* wrc = wr + (size_t)cls * 4 * CIN * MP;

    for (int ic0 = 0; ic0 < CIN; ic0 += ICB) {
        __syncthreads();
        // stage A: contiguous tf32 copy per tap, vectorized
        constexpr int A4 = ICB * MP / 4;
        for (int idx = tid; idx < 4 * A4; idx += 256) {
            int t = idx / A4, rem = idx - t * A4;
            ((uint4*)A_sm)[t * A4 + rem] =
                ((const uint4*)(wrc + (t * CIN + ic0) * MP))[rem];
        }
        // stage B: pure copy (values already tf32-rounded), vectorized loads
        constexpr int B4 = IMGB * ICB * NPIX / 4;
        for (int idx = tid; idx < B4; idx += 256) {
            int e   = idx * 4;
            int im  = e / (ICB * NPIX);
            int rem = e - im * (ICB * NPIX);
            int ic  = rem >> (2 * LOGH);
            int pix = rem & (NPIX - 1);
            int q = pix >> LOGH, r = pix & (HIN - 1);
            float4 v = *(const float4*)(in + ((size_t)(img0 + im) * CIN + ic0 + ic) * NPIX + pix);
            float* dst = (float*)(B_sm + im * (ICB * CH) + ic * CH + (q + 1) * PW + (r + 1));
            dst[0] = v.x; dst[1] = v.y; dst[2] = v.z; dst[3] = v.w;
        }
        __syncthreads();

#pragma unroll
        for (int t = 0; t < 4; t++) {
#pragma unroll
            for (int c = 0; c < KST; c++) {
                uint32_t a[2][4];
                const uint32_t* Ar = A_sm + (t * ICB + c * 8 + lt) * MP;
#pragma unroll
                for (int mm = 0; mm < 2; mm++) {
                    a[mm][0] = Ar[m0 + mm * 16 + lg];
                    a[mm][1] = Ar[m0 + mm * 16 + lg + 8];
                    a[mm][2] = Ar[4 * MP + m0 + mm * 16 + lg];
                    a[mm][3] = Ar[4 * MP + m0 + mm * 16 + lg + 8];
                }
                const int kb = (c * 8 + lt) * CH + toff[t];
#pragma unroll
                for (int s = 0; s < NSUB; s++) {
                    uint32_t b[2];
                    b[0] = B_sm[kb + base[s]];
                    b[1] = B_sm[kb + 4 * CH + base[s]];
                    mma_tf32(d[0][s], a[0], b);
                    mma_tf32(d[1][s], a[1], b);
                }
            }
        }
    }

    // epilogue: bias (+ReLU), tf32-round, scatter
#pragma unroll
    for (int mm = 0; mm < 2; mm++) {
        float bv0 = bias[m0 + mm * 16 + lg];
        float bv1 = bias[m0 + mm * 16 + lg + 8];
#pragma unroll
        for (int s = 0; s < NSUB; s++) {
            int nb = n0 + s * 8 + 2 * lt;
            int im = nb >> (2 * LOGH);
            int pix = nb & (NPIX - 1);
            int q = pix >> LOGH, r = pix & (HIN - 1);
            int oy = 2 * q + py;
            int ox0 = 2 * r + px;
            float* outb = out + (size_t)(img0 + im) * COUT * HOUT * HOUT;
#pragma unroll
            for (int half = 0; half < 2; half++) {
                int oc = m0 + mm * 16 + lg + 8 * half;
                float bv = half ? bv1 : bv0;
                float v0 = d[mm][s][2 * half]     + bv;
                float v1 = d[mm][s][2 * half + 1] + bv;
                if (RELU) { v0 = fmaxf(v0, 0.0f); v1 = fmaxf(v1, 0.0f); }
                float* orow = outb + ((size_t)oc * HOUT + oy) * HOUT;
                orow[ox0]     = tf32round(v0);
                orow[ox0 + 2] = tf32round(v1);
            }
        }
    }
}

// ---------------- conv3: fused 4 classes, swapped roles (pix=M, oc=N) --------
// Block = half an image (16 rows) for all 4 parity classes. B (padded image
// rows + halo) staged once per ic-chunk. A-fragment = pixels, B-fragment = w.
__launch_bounds__(256, 2)
__global__ void convt3_kernel(const float* __restrict__ in,
                              const uint32_t* __restrict__ wr,
                              const float* __restrict__ bias,
                              float* __restrict__ out) {
    constexpr int CIN = 64, HIN = 32, HOUT = 64;
    constexpr int PW = HIN + 2;               // 34
    constexpr int ROWS = 18;                  // 16 interior + 2 halo rows
    constexpr int CH = ((ROWS * PW - 9) / 32 + 1) * 32 + 8;  // 19*32+8 = 616
    constexpr int ICB = 8;
    constexpr int PSUB = 4;                   // 4 x 16-pixel m-tiles per warp

    extern __shared__ uint32_t smu[];
    uint32_t* A_sm = smu;                     // [4cls][4tap][ICB][8oc] = 1024
    uint32_t* B_sm = smu + 1024;              // [ICB][CH]

    const int q0 = blockIdx.x * 16;           // interior row base
    const int img = blockIdx.y;
    const int tid = threadIdx.x;
    const int warp = tid >> 5, lane = tid & 31;
    const int lg = lane >> 2, lt = lane & 3;

    for (int i = tid; i < ICB * CH; i += 256) B_sm[i] = 0;

    // per-subtile pixel base (a-frag rows): p = warp*64 + s*16 + lg
    int base[PSUB];
#pragma unroll
    for (int s = 0; s < PSUB; s++) {
        int p = warp * 64 + s * 16 + lg;
        int ql = p >> 5, r = p & 31;
        base[s] = (ql + 1) * PW + (r + 1);
    }

    float d[4][PSUB][4];
#pragma unroll
    for (int c = 0; c < 4; c++)
#pragma unroll
        for (int s = 0; s < PSUB; s++)
#pragma unroll
            for (int j = 0; j < 4; j++) d[c][s][j] = 0.0f;

    for (int ic0 = 0; ic0 < CIN; ic0 += ICB) {
        __syncthreads();
        // stage A: all cls/taps for this chunk (contiguous per cls-tap segment)
        for (int idx = tid; idx < 256; idx += 256) {
            int ct = idx / 16;                // cls*4+tap
            int rem = (idx % 16) * 4;         // within [ICB*8 = 64]
            ((uint4*)A_sm)[idx] = *(const uint4*)(wr + ct * (CIN * 8) + ic0 * 8 + rem);
        }
        // stage B: rows q0-1 .. q0+16 of each channel (zero rows stay zero)
        for (int idx = tid; idx < ICB * ROWS * 8; idx += 256) {
            int r4 = (idx & 7) * 4;
            int rr = (idx >> 3) % ROWS;
            int ic = idx / (ROWS * 8);
            int row = q0 - 1 + rr;
            if (row >= 0 && row < HIN) {
                float4 v = *(const float4*)(in + ((size_t)img * CIN + ic0 + ic) * 1024 + row * 32 + r4);
                float* dst = (float*)(B_sm + ic * CH + rr * PW + 1 + r4);
                dst[0] = v.x; dst[1] = v.y; dst[2] = v.z; dst[3] = v.w;
            }
        }
        __syncthreads();

#pragma unroll
        for (int cls = 0; cls < 4; cls++) {
            const int py = cls >> 1, px = cls & 1;
#pragma unroll
            for (int t = 0; t < 4; t++) {
                const int ra = t >> 1, rb = t & 1;
                const int toff = (py + ra) * PW + (px + rb);  // rr = ql + py+ra, col shift
                // b-frag: weights W[k=ic][n=oc]
                uint32_t b[2];
                const uint32_t* Aw = A_sm + (cls * 4 + t) * (ICB * 8);
                b[0] = Aw[lt * 8 + lg];
                b[1] = Aw[(lt + 4) * 8 + lg];
#pragma unroll
                for (int s = 0; s < PSUB; s++) {
                    uint32_t a[4];
                    const int ab = lt * CH + toff - PW - 1 + base[s];
                    a[0] = B_sm[ab];
                    a[1] = B_sm[ab + 8];          // pixel +8 (same row)
                    a[2] = B_sm[ab + 4 * CH];
                    a[3] = B_sm[ab + 4 * CH + 8];
                    mma_tf32(d[cls][s], a, b);
                }
            }
        }
    }

    // epilogue: D[pix][oc]; thread holds pixels lg, lg+8 and oc = 2lt, 2lt+1
    float bias_s[3];
    bias_s[0] = bias[0]; bias_s[1] = bias[1]; bias_s[2] = bias[2];
    float* outb = out + (size_t)img * 3 * HOUT * HOUT;
    if (lt < 2) {
#pragma unroll
        for (int cls = 0; cls < 4; cls++) {
            const int py = cls >> 1, px = cls & 1;
#pragma unroll
            for (int s = 0; s < PSUB; s++) {
#pragma unroll
                for (int rowh = 0; rowh < 2; rowh++) {
                    int p = warp * 64 + s * 16 + lg + 8 * rowh;
                    int q = q0 + (p >> 5), r = p & 31;
                    int oy = 2 * q + py, ox = 2 * r + px;
#pragma unroll
                    for (int cc = 0; cc < 2; cc++) {
                        int oc = 2 * lt + cc;
                        if (oc < 3) {
                            float v = d[cls][s][2 * rowh + cc] + bias_s[oc];
                            outb[((size_t)oc * HOUT + oy) * HOUT + ox] = v;
                        }
                    }
                }
            }
        }
    }
}

// ---------------- launch -----------------------------------------------------
extern "C" void kernel_launch(void* const* d_in, const int* in_sizes, int n_in,
                              void* d_out, int out_size) {
    const float* x  = (const float*)d_in[0];
    const float* gw = (const float*)d_in[1];
    const float* gb = (const float*)d_in[2];
    const float* z  = (const float*)d_in[3];
    const float* w1 = (const float*)d_in[4];
    const float* b1 = (const float*)d_in[5];
    const float* w2 = (const float*)d_in[6];
    const float* b2 = (const float*)d_in[7];
    const float* w3 = (const float*)d_in[8];
    const float* b3 = (const float*)d_in[9];
    float* out = (float*)d_out;

    float *lp, *bf0, *bf1, *bf2;
    uint32_t *wr1, *wr2, *wr3;
    cudaGetSymbolAddress((void**)&lp,  g_lp);
    cudaGetSymbolAddress((void**)&bf0, g_b0);
    cudaGetSymbolAddress((void**)&bf1, g_b1);
    cudaGetSymbolAddress((void**)&bf2, g_b2);
    cudaGetSymbolAddress((void**)&wr1, g_wr1);
    cudaGetSymbolAddress((void**)&wr2, g_wr2);
    cudaGetSymbolAddress((void**)&wr3, g_wr3);

    leaf_kernel<<<BATCH, 32>>>(x, gw, gb, lp);
    mix_kernel<<<dim3(8192 / 256, BATCH / 8), 256>>>(lp, z, bf0);

    prep_kernel<128, 128, 136><<<(4 * 4 * 128 * 136 + 255) / 256, 256>>>(w1, wr1);
    prep_kernel<128, 64, 72><<<(4 * 4 * 128 * 72 + 255) / 256, 256>>>(w2, wr2);
    prep3_kernel<<<(4 * 4 * 64 * 8 + 255) / 256, 256>>>(w3, wr3);

    // conv1: 128->128, 8x8 -> 16x16, ReLU.  MGRP=4, ICB=16, IMGB=2, MP=136
    // smem = A 4*16*136*4 + B 2*16*104*4 = 34816 + 13312 = 48128 B
    convt_mma3<128, 8, 128, 4, 16, 2, 136, true>
        <<<dim3(4, BATCH / 2), 256, 48128>>>(bf0, wr1, b1, bf1);
    // conv2: 128->64, 16x16 -> 32x32, ReLU. MGRP=2, ICB=16, IMGB=1, MP=72
    // smem = A 4*16*72*4 + B 16*328*4 = 18432 + 20992 = 39424 B
    convt_mma3<128, 16, 64, 2, 16, 1, 72, true>
        <<<dim3(4, BATCH), 256, 39424>>>(bf1, wr2, b2, bf2);
    // conv3: 64->3, 32x32 -> 64x64, fused classes, swapped roles.
    // smem = A 1024*4 + B 8*616*4 = 4096 + 19712 = 23808 B
    convt3_kernel<<<dim3(2, BATCH), 256, 23808>>>(bf2, wr3, b3, out);
}

// round 7
// speedup vs baseline: 5.4813x; 1.2062x over previous
#include <cuda_runtime.h>
#include <cuda_fp16.h>
#include <math.h>
#include <stdint.h>

#define BATCH 512
#define LATENT 128

// ---------------- scratch (static device arrays; no runtime allocs) ----------
__device__ float    g_lp[BATCH * 32];
__device__ uint32_t g_b0[BATCH * 64 * 64];        // half2-packed [n][icp64][pix64]
__device__ uint32_t g_b1[BATCH * 64 * 256];       // [n][ocp64][pix256]
__device__ uint32_t g_b2[BATCH * 32 * 1024];      // [n][ocp32][pix1024]
// half2-pair-packed weights
__device__ uint32_t g_wr1[4 * 4 * 64 * 136];      // [cls][tap][icp][MP]
__device__ uint32_t g_wr2[4 * 4 * 64 * 72];
__device__ uint32_t g_wr3[4 * 4 * 32 * 8];        // [cls][tap][icp][8 oc]

// ---------------- helpers ----------------
__device__ __forceinline__ uint32_t packh2(float lo, float hi) {
    __half2 h = __floats2half2_rn(lo, hi);
    return *(uint32_t*)&h;
}
__device__ __forceinline__ void mma_f16(float* d, const uint32_t* a, const uint32_t* b) {
    asm("mma.sync.aligned.m16n8k16.row.col.f32.f16.f16.f32 "
        "{%0,%1,%2,%3}, {%4,%5,%6,%7}, {%8,%9}, {%0,%1,%2,%3};"
        : "+f"(d[0]), "+f"(d[1]), "+f"(d[2]), "+f"(d[3])
        : "r"(a[0]), "r"(a[1]), "r"(a[2]), "r"(a[3]), "r"(b[0]), "r"(b[1]));
}

// ---------------- stage 1: gating + soft-tree leaf probabilities -------------
__global__ void leaf_kernel(const float* __restrict__ x,
                            const float* __restrict__ gw,
                            const float* __restrict__ gb,
                            float* __restrict__ lp) {
    int b = blockIdx.x;
    int lane = threadIdx.x;
    __shared__ float xs[LATENT];
    __shared__ float gs[32];
    for (int k = lane; k < LATENT; k += 32) xs[k] = x[b * LATENT + k];
    __syncthreads();
    if (lane < 31) {
        float acc = gb[lane];
#pragma unroll 8
        for (int k = 0; k < LATENT; k++) acc += xs[k] * gw[k * 31 + lane];
        gs[lane] = 1.0f / (1.0f + expf(-acc));
    }
    __syncthreads();
    float dens = 1.0f;
    int l = lane;
#pragma unroll
    for (int d = 1; d <= 5; d++) {
        int par  = l >> (6 - d);
        int gate = (1 << (d - 1)) - 1 + par;
        int bit  = (l >> (5 - d)) & 1;
        float gv = gs[gate];
        dens *= bit ? (1.0f - gv) : gv;
    }
    lp[b * 32 + l] = dens;
}

// ---------------- stage 2: mix, writes half2 channel-pair words --------------
// thread owns (icp, pix): channels 2icp & 2icp+1 at one pixel, 8 batches.
__global__ void mix_kernel(const float* __restrict__ lp,
                           const float* __restrict__ z,
                           uint32_t* __restrict__ out0) {
    __shared__ float lps[8][32];
    int tid = threadIdx.x;
    int idx = blockIdx.x * 256 + tid;          // [0, 4096)
    int b0 = blockIdx.y * 8;
    lps[tid >> 5][tid & 31] = lp[b0 * 32 + tid];
    __syncthreads();
    int icp = idx >> 6, pix = idx & 63;
    const float4* z0 = (const float4*)(z + (size_t)(icp * 128 + pix) * 32);
    const float4* z1 = (const float4*)(z + (size_t)(icp * 128 + 64 + pix) * 32);
    float4 zr0[8], zr1[8];
#pragma unroll
    for (int j = 0; j < 8; j++) { zr0[j] = z0[j]; zr1[j] = z1[j]; }
#pragma unroll
    for (int bb = 0; bb < 8; bb++) {
        const float* lr = lps[bb];
        float a0 = 0.0f, a1 = 0.0f;
#pragma unroll
        for (int j = 0; j < 8; j++) {
            float4 u = zr0[j], v = zr1[j];
            a0 += u.x * lr[4 * j] + u.y * lr[4 * j + 1] + u.z * lr[4 * j + 2] + u.w * lr[4 * j + 3];
            a1 += v.x * lr[4 * j] + v.y * lr[4 * j + 1] + v.z * lr[4 * j + 2] + v.w * lr[4 * j + 3];
        }
        out0[(size_t)(b0 + bb) * 4096 + idx] = packh2(a0, a1);
    }
}

// ---------------- weight prep (conv1/conv2) ----------------------------------
template <int CIN, int COUT, int MP>
__global__ void prep_h2(const float* __restrict__ w, uint32_t* __restrict__ wr) {
    int idx = blockIdx.x * 256 + threadIdx.x;
    if (idx >= 4 * 4 * (CIN / 2) * MP) return;
    int m   = idx % MP;
    int t2  = idx / MP;
    int icp = t2 % (CIN / 2);
    int t3  = t2 / (CIN / 2);
    int tap = t3 & 3;
    int cls = t3 >> 2;
    int py = cls >> 1, px = cls & 1;
    int ra = tap >> 1, rb = tap & 1;
    int ky = 3 - py - 2 * ra;
    int kx = 3 - px - 2 * rb;
    float v0 = 0.0f, v1 = 0.0f;
    if (m < COUT) {
        v0 = w[((size_t)(2 * icp) * COUT + m) * 16 + ky * 4 + kx];
        v1 = w[((size_t)(2 * icp + 1) * COUT + m) * 16 + ky * 4 + kx];
    }
    wr[idx] = packh2(v0, v1);
}

// ---------------- weight prep (conv3) ----------------------------------------
__global__ void prep3_h2(const float* __restrict__ w, uint32_t* __restrict__ wr) {
    int idx = blockIdx.x * 256 + threadIdx.x;
    if (idx >= 4 * 4 * 32 * 8) return;
    int oc  = idx & 7;
    int icp = (idx >> 3) & 31;
    int tap = (idx >> 8) & 3;
    int cls = idx >> 10;
    int py = cls >> 1, px = cls & 1;
    int ra = tap >> 1, rb = tap & 1;
    int ky = 3 - py - 2 * ra;
    int kx = 3 - px - 2 * rb;
    float v0 = 0.0f, v1 = 0.0f;
    if (oc < 3) {
        v0 = w[((size_t)(2 * icp) * 3 + oc) * 16 + ky * 4 + kx];
        v1 = w[((size_t)(2 * icp + 1) * 3 + oc) * 16 + ky * 4 + kx];
    }
    wr[idx] = packh2(v0, v1);
}

// ---------------- conv1/conv2: fp16 m16n8k16, halo-padded half2 B ------------
template <int CIN, int HIN, int COUT, int MGRP, int IMGB, int MP, bool RELU>
__launch_bounds__(256, 2)
__global__ void convt_h2(const uint32_t* __restrict__ in,
                         const uint32_t* __restrict__ wr,
                         const float* __restrict__ bias,
                         uint32_t* __restrict__ out) {
    constexpr int NPIX = HIN * HIN;
    constexpr int HOUT = 2 * HIN;
    constexpr int PW   = HIN + 2;
    constexpr int PP   = PW * PW;
    constexpr int CH   = ((PP - 9) / 32 + 1) * 32 + 8;   // word stride ==8 mod 32
    constexpr int NGRP = 8 / MGRP;
    constexpr int NTOT = IMGB * NPIX;
    constexpr int NSUB = NTOT / (8 * NGRP);
    constexpr int LOGH = (HIN == 8) ? 3 : 4;
    constexpr int ICP  = CIN / 2;

    extern __shared__ uint32_t smu[];
    uint32_t* A_sm = smu;                    // [4 taps][8 icp][MP]
    uint32_t* B_sm = smu + 4 * 8 * MP;       // [IMGB][8 icp][CH]

    const int cls = blockIdx.x;
    const int img0 = blockIdx.y * IMGB;
    const int py = cls >> 1, px = cls & 1;
    const int tid = threadIdx.x;
    const int warp = tid >> 5, lane = tid & 31;
    const int lg = lane >> 2, lt = lane & 3;
    const int m0 = (warp % MGRP) * 32;
    const int n0 = (warp / MGRP) * (NSUB * 8);

    for (int i = tid; i < IMGB * 8 * CH; i += 256) B_sm[i] = 0;

    int toff[4];
#pragma unroll
    for (int t = 0; t < 4; t++)
        toff[t] = (py - 1 + (t >> 1)) * PW + (px - 1 + (t & 1));

    int base[NSUB];
#pragma unroll
    for (int s = 0; s < NSUB; s++) {
        int n = n0 + s * 8 + lg;
        int im = n >> (2 * LOGH);
        int pix = n & (NPIX - 1);
        int q = pix >> LOGH, r = pix & (HIN - 1);
        base[s] = im * (8 * CH) + (q + 1) * PW + (r + 1);
    }

    float d[2][NSUB][4];
#pragma unroll
    for (int mm = 0; mm < 2; mm++)
#pragma unroll
        for (int s = 0; s < NSUB; s++)
#pragma unroll
            for (int j = 0; j < 4; j++) d[mm][s][j] = 0.0f;

    const uint32_t* wrc = wr + (size_t)cls * 4 * ICP * MP;

    for (int icp0 = 0; icp0 < ICP; icp0 += 8) {
        __syncthreads();
        // stage A: 4 taps x 8 icp x MP, contiguous per tap
        constexpr int A4 = 8 * MP / 4;
        for (int idx = tid; idx < 4 * A4; idx += 256) {
            int t = idx / A4, rem = idx - t * A4;
            ((uint4*)A_sm)[t * A4 + rem] =
                ((const uint4*)(wrc + (t * ICP + icp0) * MP))[rem];
        }
        // stage B: pure packed copy into padded interior
        constexpr int B4 = IMGB * 8 * NPIX / 4;
        for (int idx = tid; idx < B4; idx += 256) {
            int e   = idx * 4;
            int im  = e / (8 * NPIX);
            int rem = e - im * (8 * NPIX);
            int icp = rem >> (2 * LOGH);
            int pix = rem & (NPIX - 1);
            int q = pix >> LOGH, r = pix & (HIN - 1);
            uint4 v = *(const uint4*)(in + ((size_t)(img0 + im) * ICP + icp0 + icp) * NPIX + pix);
            uint32_t* dst = B_sm + im * (8 * CH) + icp * CH + (q + 1) * PW + (r + 1);
            dst[0] = v.x; dst[1] = v.y; dst[2] = v.z; dst[3] = v.w;
        }
        __syncthreads();

#pragma unroll
        for (int t = 0; t < 4; t++) {
            uint32_t a[2][4];
            const uint32_t* Ar0 = A_sm + (t * 8 + lt) * MP;
            const uint32_t* Ar1 = A_sm + (t * 8 + lt + 4) * MP;
#pragma unroll
            for (int mm = 0; mm < 2; mm++) {
                a[mm][0] = Ar0[m0 + mm * 16 + lg];
                a[mm][1] = Ar0[m0 + mm * 16 + lg + 8];
                a[mm][2] = Ar1[m0 + mm * 16 + lg];
                a[mm][3] = Ar1[m0 + mm * 16 + lg + 8];
            }
            const int kb = lt * CH + toff[t];
#pragma unroll
            for (int s = 0; s < NSUB; s++) {
                uint32_t b[2];
                b[0] = B_sm[kb + base[s]];
                b[1] = B_sm[kb + 4 * CH + base[s]];
                mma_f16(d[0][s], a[0], b);
                mma_f16(d[1][s], a[1], b);
            }
        }
    }

    // epilogue: bias(+ReLU), pair-exchange via shfl, write packed half2 words
    constexpr int HO2 = HOUT * HOUT;
    float bv[2][2];
#pragma unroll
    for (int mm = 0; mm < 2; mm++) {
        bv[mm][0] = bias[m0 + mm * 16 + lg];
        bv[mm][1] = bias[m0 + mm * 16 + lg + 8];
    }
#pragma unroll
    for (int mm = 0; mm < 2; mm++) {
#pragma unroll
        for (int s = 0; s < NSUB; s++) {
            int nb = n0 + s * 8 + 2 * lt;
            int im = nb >> (2 * LOGH);
            int pix = nb & (NPIX - 1);
            int q = pix >> LOGH, r = pix & (HIN - 1);
            int op0 = (2 * q + py) * HOUT + 2 * r + px;
            uint32_t* outw = out + (size_t)(img0 + im) * (COUT / 2) * HO2;
#pragma unroll
            for (int half = 0; half < 2; half++) {
                int oc = m0 + mm * 16 + lg + 8 * half;
                float v0 = d[mm][s][2 * half]     + bv[mm][half];
                float v1 = d[mm][s][2 * half + 1] + bv[mm][half];
                if (RELU) { v0 = fmaxf(v0, 0.0f); v1 = fmaxf(v1, 0.0f); }
                float p0 = __shfl_down_sync(0xffffffffu, v0, 4);
                float p1 = __shfl_down_sync(0xffffffffu, v1, 4);
                if (!(lg & 1)) {
                    int ocp = oc >> 1;
                    outw[(size_t)ocp * HO2 + op0]     = packh2(v0, p0);
                    outw[(size_t)ocp * HO2 + op0 + 2] = packh2(v1, p1);
                }
            }
        }
    }
}

// ---------------- conv3: fused classes, swapped roles, fp16 k16 --------------
__launch_bounds__(256, 2)
__global__ void convt3_h2(const uint32_t* __restrict__ in,
                          const uint32_t* __restrict__ wr,
                          const float* __restrict__ bias,
                          float* __restrict__ out) {
    constexpr int HIN = 32, HOUT = 64;
    constexpr int PW = HIN + 2;               // 34
    constexpr int ROWS = 18;
    constexpr int CH = ((ROWS * PW - 9) / 32 + 1) * 32 + 8;  // 616
    constexpr int PSUB = 4;

    extern __shared__ uint32_t smu[];
    uint32_t* A_sm = smu;                     // [16 ct][8 icp][8 oc] = 1024 words
    uint32_t* B_sm = smu + 1024;              // [8 icp][CH]

    const int q0 = blockIdx.x * 16;
    const int img = blockIdx.y;
    const int tid = threadIdx.x;
    const int warp = tid >> 5, lane = tid & 31;
    const int lg = lane >> 2, lt = lane & 3;

    for (int i = tid; i < 8 * CH; i += 256) B_sm[i] = 0;

    int base[PSUB];
#pragma unroll
    for (int s = 0; s < PSUB; s++) {
        int p = warp * 64 + s * 16 + lg;
        int ql = p >> 5, r = p & 31;
        base[s] = (ql + 1) * PW + (r + 1);
    }

    float d[4][PSUB][4];
#pragma unroll
    for (int c = 0; c < 4; c++)
#pragma unroll
        for (int s = 0; s < PSUB; s++)
#pragma unroll
            for (int j = 0; j < 4; j++) d[c][s][j] = 0.0f;

    for (int icp0 = 0; icp0 < 32; icp0 += 8) {
        __syncthreads();
        // stage A: 16 cls-taps x (8 icp x 8 oc)
        for (int idx = tid; idx < 256; idx += 256) {
            int ct = idx / 16, r4 = idx % 16;
            ((uint4*)A_sm)[idx] = ((const uint4*)(wr + ct * 256 + icp0 * 8))[r4];
        }
        // stage B: rows q0-1 .. q0+16 of 8 icp rows
        for (int idx = tid; idx < 8 * ROWS * 8; idx += 256) {
            int r4 = (idx & 7) * 4;
            int rr = (idx >> 3) % ROWS;
            int icp = idx / (ROWS * 8);
            int row = q0 - 1 + rr;
            if (row >= 0 && row < HIN) {
                uint4 v = *(const uint4*)(in + ((size_t)img * 32 + icp0 + icp) * 1024 + row * 32 + r4);
                uint32_t* dst = B_sm + icp * CH + rr * PW + 1 + r4;
                dst[0] = v.x; dst[1] = v.y; dst[2] = v.z; dst[3] = v.w;
            }
        }
        __syncthreads();

#pragma unroll
        for (int cls = 0; cls < 4; cls++) {
            const int py = cls >> 1, px = cls & 1;
#pragma unroll
            for (int t = 0; t < 4; t++) {
                const int ra = t >> 1, rb = t & 1;
                const int toff = (py + ra) * PW + (px + rb);
                uint32_t b[2];
                const uint32_t* Aw = A_sm + (cls * 4 + t) * 64;
                b[0] = Aw[lt * 8 + lg];
                b[1] = Aw[(lt + 4) * 8 + lg];
#pragma unroll
                for (int s = 0; s < PSUB; s++) {
                    uint32_t a[4];
                    const int ab = lt * CH + toff - PW - 1 + base[s];
                    a[0] = B_sm[ab];
                    a[1] = B_sm[ab + 8];
                    a[2] = B_sm[ab + 4 * CH];
                    a[3] = B_sm[ab + 4 * CH + 8];
                    mma_f16(d[cls][s], a, b);
                }
            }
        }
    }

    float bias_s[3];
    bias_s[0] = bias[0]; bias_s[1] = bias[1]; bias_s[2] = bias[2];
    float* outb = out + (size_t)img * 3 * HOUT * HOUT;
    if (lt < 2) {
#pragma unroll
        for (int cls = 0; cls < 4; cls++) {
            const int py = cls >> 1, px = cls & 1;
#pragma unroll
            for (int s = 0; s < PSUB; s++) {
#pragma unroll
                for (int rowh = 0; rowh < 2; rowh++) {
                    int p = warp * 64 + s * 16 + lg + 8 * rowh;
                    int q = q0 + (p >> 5), r = p & 31;
                    int oy = 2 * q + py, ox = 2 * r + px;
#pragma unroll
                    for (int cc = 0; cc < 2; cc++) {
                        int oc = 2 * lt + cc;
                        if (oc < 3) {
                            float v = d[cls][s][2 * rowh + cc] + bias_s[oc];
                            outb[((size_t)oc * HOUT + oy) * HOUT + ox] = v;
                        }
                    }
                }
            }
        }
    }
}

// ---------------- launch -----------------------------------------------------
extern "C" void kernel_launch(void* const* d_in, const int* in_sizes, int n_in,
                              void* d_out, int out_size) {
    const float* x  = (const float*)d_in[0];
    const float* gw = (const float*)d_in[1];
    const float* gb = (const float*)d_in[2];
    const float* z  = (const float*)d_in[3];
    const float* w1 = (const float*)d_in[4];
    const float* b1 = (const float*)d_in[5];
    const float* w2 = (const float*)d_in[6];
    const float* b2 = (const float*)d_in[7];
    const float* w3 = (const float*)d_in[8];
    const float* b3 = (const float*)d_in[9];
    float* out = (float*)d_out;

    float *lp;
    uint32_t *bf0, *bf1, *bf2, *wr1, *wr2, *wr3;
    cudaGetSymbolAddress((void**)&lp,  g_lp);
    cudaGetSymbolAddress((void**)&bf0, g_b0);
    cudaGetSymbolAddress((void**)&bf1, g_b1);
    cudaGetSymbolAddress((void**)&bf2, g_b2);
    cudaGetSymbolAddress((void**)&wr1, g_wr1);
    cudaGetSymbolAddress((void**)&wr2, g_wr2);
    cudaGetSymbolAddress((void**)&wr3, g_wr3);

    leaf_kernel<<<BATCH, 32>>>(x, gw, gb, lp);
    mix_kernel<<<dim3(16, BATCH / 8), 256>>>(lp, z, bf0);

    prep_h2<128, 128, 136><<<(4 * 4 * 64 * 136 + 255) / 256, 256>>>(w1, wr1);
    prep_h2<128, 64, 72><<<(4 * 4 * 64 * 72 + 255) / 256, 256>>>(w2, wr2);
    prep3_h2<<<(4 * 4 * 32 * 8 + 255) / 256, 256>>>(w3, wr3);

    // conv1: 128->128, 8x8 -> 16x16, ReLU. MGRP=4, IMGB=2, MP=136
    // smem = A 4*8*136*4 + B 2*8*104*4 = 17408 + 6656 = 24064 B
    convt_h2<128, 8, 128, 4, 2, 136, true>
        <<<dim3(4, BATCH / 2), 256, 24064>>>(bf0, wr1, b1, bf1);
    // conv2: 128->64, 16x16 -> 32x32, ReLU. MGRP=2, IMGB=1, MP=72
    // smem = A 4*8*72*4 + B 8*328*4 = 9216 + 10496 = 19712 B
    convt_h2<128, 16, 64, 2, 1, 72, true>
        <<<dim3(4, BATCH), 256, 19712>>>(bf1, wr2, b2, bf2);
    // conv3: 64->3, 32x32 -> 64x64. smem = 1024*4 + 8*616*4 = 23808 B
    convt3_h2<<<dim3(2, BATCH), 256, 23808>>>(bf2, wr3, b3, out);
}

// round 9
// speedup vs baseline: 7.9813x; 1.4561x over previous
#include <cuda_runtime.h>
#include <cuda_fp16.h>
#include <math.h>
#include <stdint.h>

#define BATCH 512
#define LATENT 128

// ---------------- scratch (static device arrays; no runtime allocs) ----------
__device__ float    g_lp[BATCH * 32];
__device__ uint32_t g_b0[BATCH * 64 * 64];        // half2-packed [n][icp64][pix64]
__device__ uint32_t g_b1[BATCH * 64 * 256];       // [n][ocp64][pix256]
__device__ uint32_t g_b2[BATCH * 32 * 1024];      // [n][ocp32][pix1024]
// half2-pair-packed weights
__device__ uint32_t g_wr1[4 * 4 * 64 * 136];      // [cls][tap][icp][MP]
__device__ uint32_t g_wr2[4 * 4 * 64 * 72];
__device__ uint32_t g_wr3[4 * 4 * 32 * 8];        // [cls][tap][icp][8 oc]

// ---------------- helpers ----------------
__device__ __forceinline__ uint32_t packh2(float lo, float hi) {
    __half2 h = __floats2half2_rn(lo, hi);
    return *(uint32_t*)&h;
}
__device__ __forceinline__ void mma_f16(float* d, const uint32_t* a, const uint32_t* b) {
    asm("mma.sync.aligned.m16n8k16.row.col.f32.f16.f16.f32 "
        "{%0,%1,%2,%3}, {%4,%5,%6,%7}, {%8,%9}, {%0,%1,%2,%3};"
        : "+f"(d[0]), "+f"(d[1]), "+f"(d[2]), "+f"(d[3])
        : "r"(a[0]), "r"(a[1]), "r"(a[2]), "r"(a[3]), "r"(b[0]), "r"(b[1]));
}
__device__ __forceinline__ void cp16(uint32_t* dst, const void* src) {
    uint32_t s = (uint32_t)__cvta_generic_to_shared(dst);
    asm volatile("cp.async.ca.shared.global [%0], [%1], 16;" :: "r"(s), "l"(src) : "memory");
}
__device__ __forceinline__ void cp_commit() {
    asm volatile("cp.async.commit_group;" ::: "memory");
}
template <int N>
__device__ __forceinline__ void cp_wait() {
    asm volatile("cp.async.wait_group %0;" :: "n"(N) : "memory");
}

// ---------------- stage 1: gating + soft-tree leaf probabilities -------------
__global__ void leaf_kernel(const float* __restrict__ x,
                            const float* __restrict__ gw,
                            const float* __restrict__ gb,
                            float* __restrict__ lp) {
    int b = blockIdx.x;
    int lane = threadIdx.x;
    __shared__ float xs[LATENT];
    __shared__ float gs[32];
    for (int k = lane; k < LATENT; k += 32) xs[k] = x[b * LATENT + k];
    __syncthreads();
    if (lane < 31) {
        float acc = gb[lane];
#pragma unroll 8
        for (int k = 0; k < LATENT; k++) acc += xs[k] * gw[k * 31 + lane];
        gs[lane] = 1.0f / (1.0f + expf(-acc));
    }
    __syncthreads();
    float dens = 1.0f;
    int l = lane;
#pragma unroll
    for (int d = 1; d <= 5; d++) {
        int par  = l >> (6 - d);
        int gate = (1 << (d - 1)) - 1 + par;
        int bit  = (l >> (5 - d)) & 1;
        float gv = gs[gate];
        dens *= bit ? (1.0f - gv) : gv;
    }
    lp[b * 32 + l] = dens;
}

// ---------------- stage 2: mix, writes half2 channel-pair words --------------
__global__ void mix_kernel(const float* __restrict__ lp,
                           const float* __restrict__ z,
                           uint32_t* __restrict__ out0) {
    __shared__ float lps[8][32];
    int tid = threadIdx.x;
    int idx = blockIdx.x * 256 + tid;          // [0, 4096)
    int b0 = blockIdx.y * 8;
    lps[tid >> 5][tid & 31] = lp[b0 * 32 + tid];
    __syncthreads();
    int icp = idx >> 6, pix = idx & 63;
    const float4* z0 = (const float4*)(z + (size_t)(icp * 128 + pix) * 32);
    const float4* z1 = (const float4*)(z + (size_t)(icp * 128 + 64 + pix) * 32);
    float4 zr0[8], zr1[8];
#pragma unroll
    for (int j = 0; j < 8; j++) { zr0[j] = z0[j]; zr1[j] = z1[j]; }
#pragma unroll
    for (int bb = 0; bb < 8; bb++) {
        const float* lr = lps[bb];
        float a0 = 0.0f, a1 = 0.0f;
#pragma unroll
        for (int j = 0; j < 8; j++) {
            float4 u = zr0[j], v = zr1[j];
            a0 += u.x * lr[4 * j] + u.y * lr[4 * j + 1] + u.z * lr[4 * j + 2] + u.w * lr[4 * j + 3];
            a1 += v.x * lr[4 * j] + v.y * lr[4 * j + 1] + v.z * lr[4 * j + 2] + v.w * lr[4 * j + 3];
        }
        out0[(size_t)(b0 + bb) * 4096 + idx] = packh2(a0, a1);
    }
}

// ---------------- merged weight prep -----------------------------------------
__device__ __forceinline__ void prep_common(const float* __restrict__ w,
                                            uint32_t* __restrict__ wr,
                                            int idx, int CIN, int COUT, int MP) {
    if (idx >= 4 * 4 * (CIN / 2) * MP) return;
    int m   = idx % MP;
    int t2  = idx / MP;
    int icp = t2 % (CIN / 2);
    int t3  = t2 / (CIN / 2);
    int tap = t3 & 3;
    int cls = t3 >> 2;
    int py = cls >> 1, px = cls & 1;
    int ra = tap >> 1, rb = tap & 1;
    int ky = 3 - py - 2 * ra;
    int kx = 3 - px - 2 * rb;
    float v0 = 0.0f, v1 = 0.0f;
    if (m < COUT) {
        v0 = w[((size_t)(2 * icp) * COUT + m) * 16 + ky * 4 + kx];
        v1 = w[((size_t)(2 * icp + 1) * COUT + m) * 16 + ky * 4 + kx];
    }
    wr[idx] = packh2(v0, v1);
}

__global__ void prep_all(const float* __restrict__ w1, uint32_t* __restrict__ wr1,
                         const float* __restrict__ w2, uint32_t* __restrict__ wr2,
                         const float* __restrict__ w3, uint32_t* __restrict__ wr3) {
    int g = blockIdx.x;
    int tid = threadIdx.x;
    if (g < 544)      prep_common(w1, wr1, g * 256 + tid, 128, 128, 136);
    else if (g < 832) prep_common(w2, wr2, (g - 544) * 256 + tid, 128, 64, 72);
    else              prep_common(w3, wr3, (g - 832) * 256 + tid, 64, 3, 8);
}

// ---------------- conv1/conv2: fp16 mma, cp.async double-buffered ------------
// Padded image: row stride RS words (interior at word 4, 16B aligned),
// channel stride CH words (== 8 mod 32 for conflict-free fragment loads).
template <int CIN, int HIN, int COUT, int MGRP, int IMGB, int MP, int RS, int CH, bool RELU>
__launch_bounds__(256, 2)
__global__ void convt_h2(const uint32_t* __restrict__ in,
                         const uint32_t* __restrict__ wr,
                         const float* __restrict__ bias,
                         uint32_t* __restrict__ out) {
    constexpr int NPIX = HIN * HIN;
    constexpr int HOUT = 2 * HIN;
    constexpr int NGRP = 8 / MGRP;
    constexpr int NTOT = IMGB * NPIX;
    constexpr int NSUB = NTOT / (8 * NGRP);
    constexpr int LOGH = (HIN == 8) ? 3 : 4;
    constexpr int ICP  = CIN / 2;
    constexpr int NCH  = ICP / 8;
    constexpr int ASZ  = 4 * 8 * MP;      // words per A stage
    constexpr int BSZ  = IMGB * 8 * CH;   // words per B stage

    extern __shared__ uint32_t smu[];
    uint32_t* Abuf[2] = { smu, smu + ASZ };
    uint32_t* Bbuf[2] = { smu + 2 * ASZ, smu + 2 * ASZ + BSZ };

    const int cls = blockIdx.x;
    const int img0 = blockIdx.y * IMGB;
    const int py = cls >> 1, px = cls & 1;
    const int tid = threadIdx.x;
    const int warp = tid >> 5, lane = tid & 31;
    const int lg = lane >> 2, lt = lane & 3;
    const int m0 = (warp % MGRP) * 32;
    const int n0 = (warp / MGRP) * (NSUB * 8);

    for (int i = tid; i < 2 * BSZ; i += 256) Bbuf[0][i] = 0;   // both buffers
    __syncthreads();

    int toff[4];
#pragma unroll
    for (int t = 0; t < 4; t++)
        toff[t] = (py - 1 + (t >> 1)) * RS + (px - 1 + (t & 1));

    int base[NSUB];
#pragma unroll
    for (int s = 0; s < NSUB; s++) {
        int n = n0 + s * 8 + lg;
        int im = n >> (2 * LOGH);
        int pix = n & (NPIX - 1);
        int q = pix >> LOGH, r = pix & (HIN - 1);
        base[s] = im * (8 * CH) + (q + 1) * RS + 4 + r;
    }

    float d[2][NSUB][4];
#pragma unroll
    for (int mm = 0; mm < 2; mm++)
#pragma unroll
        for (int s = 0; s < NSUB; s++)
#pragma unroll
            for (int j = 0; j < 4; j++) d[mm][s][j] = 0.0f;

    const uint32_t* wrc = wr + (size_t)cls * 4 * ICP * MP;

    auto prefetch = [&](int c) {
        int buf = c & 1;
        int icp0 = c * 8;
        uint32_t* A = Abuf[buf];
        uint32_t* B = Bbuf[buf];
        constexpr int A4 = 8 * MP / 4;
        for (int idx = tid; idx < 4 * A4; idx += 256) {
            int t = idx / A4, rem = idx - t * A4;
            cp16(A + t * (8 * MP) + rem * 4, wrc + (t * ICP + icp0) * MP + rem * 4);
        }
        constexpr int B4 = IMGB * 8 * NPIX / 4;
        for (int idx = tid; idx < B4; idx += 256) {
            int e   = idx * 4;
            int im  = e / (8 * NPIX);
            int rem = e - im * (8 * NPIX);
            int icp = rem >> (2 * LOGH);
            int pix = rem & (NPIX - 1);
            int q = pix >> LOGH, r = pix & (HIN - 1);
            cp16(B + im * (8 * CH) + icp * CH + (q + 1) * RS + 4 + r,
                 in + ((size_t)(img0 + im) * ICP + icp0 + icp) * NPIX + pix);
        }
    };

    prefetch(0);
    cp_commit();

    for (int c = 0; c < NCH; c++) {
        if (c + 1 < NCH) { prefetch(c + 1); cp_commit(); cp_wait<1>(); }
        else             { cp_wait<0>(); }
        __syncthreads();
        const uint32_t* A_sm = Abuf[c & 1];
        const uint32_t* B_sm = Bbuf[c & 1];

#pragma unroll
        for (int t = 0; t < 4; t++) {
            uint32_t a[2][4];
            const uint32_t* Ar0 = A_sm + (t * 8 + lt) * MP;
            const uint32_t* Ar1 = A_sm + (t * 8 + lt + 4) * MP;
#pragma unroll
            for (int mm = 0; mm < 2; mm++) {
                a[mm][0] = Ar0[m0 + mm * 16 + lg];
                a[mm][1] = Ar0[m0 + mm * 16 + lg + 8];
                a[mm][2] = Ar1[m0 + mm * 16 + lg];
                a[mm][3] = Ar1[m0 + mm * 16 + lg + 8];
            }
            const int kb = lt * CH + toff[t];
#pragma unroll
            for (int s = 0; s < NSUB; s++) {
                uint32_t b[2];
                b[0] = B_sm[kb + base[s]];
                b[1] = B_sm[kb + 4 * CH + base[s]];
                mma_f16(d[0][s], a[0], b);
                mma_f16(d[1][s], a[1], b);
            }
        }
        __syncthreads();
    }

    // epilogue: bias(+ReLU), pair-exchange via shfl, write packed half2 words
    constexpr int HO2 = HOUT * HOUT;
    float bv[2][2];
#pragma unroll
    for (int mm = 0; mm < 2; mm++) {
        bv[mm][0] = bias[m0 + mm * 16 + lg];
        bv[mm][1] = bias[m0 + mm * 16 + lg + 8];
    }
#pragma unroll
    for (int mm = 0; mm < 2; mm++) {
#pragma unroll
        for (int s = 0; s < NSUB; s++) {
            int nb = n0 + s * 8 + 2 * lt;
            int im = nb >> (2 * LOGH);
            int pix = nb & (NPIX - 1);
            int q = pix >> LOGH, r = pix & (HIN - 1);
            int op0 = (2 * q + py) * HOUT + 2 * r + px;
            uint32_t* outw = out + (size_t)(img0 + im) * (COUT / 2) * HO2;
#pragma unroll
            for (int half = 0; half < 2; half++) {
                int oc = m0 + mm * 16 + lg + 8 * half;
                float v0 = d[mm][s][2 * half]     + bv[mm][half];
                float v1 = d[mm][s][2 * half + 1] + bv[mm][half];
                if (RELU) { v0 = fmaxf(v0, 0.0f); v1 = fmaxf(v1, 0.0f); }
                float p0 = __shfl_down_sync(0xffffffffu, v0, 4);
                float p1 = __shfl_down_sync(0xffffffffu, v1, 4);
                if (!(lg & 1)) {
                    int ocp = oc >> 1;
                    outw[(size_t)ocp * HO2 + op0]     = packh2(v0, p0);
                    outw[(size_t)ocp * HO2 + op0 + 2] = packh2(v1, p1);
                }
            }
        }
    }
}

// ---------------- conv3: fused classes, swapped roles, cp.async pipeline -----
__launch_bounds__(256, 2)
__global__ void convt3_h2(const uint32_t* __restrict__ in,
                          const uint32_t* __restrict__ wr,
                          const float* __restrict__ bias,
                          float* __restrict__ out) {
    constexpr int HIN = 32, HOUT = 64;
    constexpr int RS = 40;                    // row stride, interior at word 4
    constexpr int ROWS = 18;
    constexpr int CH = 744;                   // >= 18*40, == 8 mod 32
    constexpr int PSUB = 4;
    constexpr int ASZ = 1024;                 // [16 ct][8 icp][8 oc]
    constexpr int BSZ = 8 * CH;

    extern __shared__ uint32_t smu[];
    uint32_t* Abuf[2] = { smu, smu + ASZ };
    uint32_t* Bbuf[2] = { smu + 2 * ASZ, smu + 2 * ASZ + BSZ };

    const int q0 = blockIdx.x * 16;
    const int img = blockIdx.y;
    const int tid = threadIdx.x;
    const int warp = tid >> 5, lane = tid & 31;
    const int lg = lane >> 2, lt = lane & 3;

    for (int i = tid; i < 2 * BSZ; i += 256) Bbuf[0][i] = 0;
    __syncthreads();

    int base[PSUB];
#pragma unroll
    for (int s = 0; s < PSUB; s++) {
        int p = warp * 64 + s * 16 + lg;
        int ql = p >> 5, r = p & 31;
        base[s] = (ql + 1) * RS + 4 + r;
    }

    float d[4][PSUB][4];
#pragma unroll
    for (int c = 0; c < 4; c++)
#pragma unroll
        for (int s = 0; s < PSUB; s++)
#pragma unroll
            for (int j = 0; j < 4; j++) d[c][s][j] = 0.0f;

    auto prefetch = [&](int c) {
        int buf = c & 1;
        int icp0 = c * 8;
        uint32_t* A = Abuf[buf];
        uint32_t* B = Bbuf[buf];
        // A chunk = 16 cls-taps x 8 icp x 8 oc = 1024 words = 256 uint4
        // (round-8 bug: this bound was 64 -> 12/16 cls-tap segments stayed
        //  uninitialized garbage; must be 256)
        for (int idx = tid; idx < 256; idx += 256) {
            int ct = idx >> 4, r4 = idx & 15;
            cp16(A + ct * 64 + r4 * 4, wr + ct * 256 + icp0 * 8 + r4 * 4);
        }
        for (int idx = tid; idx < 8 * ROWS * 8; idx += 256) {
            int r4 = (idx & 7) * 4;
            int rr = (idx >> 3) % ROWS;
            int icp = idx / (ROWS * 8);
            int row = q0 - 1 + rr;
            if (row >= 0 && row < HIN)
                cp16(B + icp * CH + rr * RS + 4 + r4,
                     in + ((size_t)img * 32 + icp0 + icp) * 1024 + row * 32 + r4);
        }
    };

    prefetch(0);
    cp_commit();

    for (int c = 0; c < 4; c++) {
        if (c + 1 < 4) { prefetch(c + 1); cp_commit(); cp_wait<1>(); }
        else           { cp_wait<0>(); }
        __syncthreads();
        const uint32_t* A_sm = Abuf[c & 1];
        const uint32_t* B_sm = Bbuf[c & 1];

#pragma unroll
        for (int cls = 0; cls < 4; cls++) {
            const int py = cls >> 1, px = cls & 1;
#pragma unroll
            for (int t = 0; t < 4; t++) {
                const int ra = t >> 1, rb = t & 1;
                const int toff = (py + ra) * RS + (px + rb);
                uint32_t b[2];
                const uint32_t* Aw = A_sm + (cls * 4 + t) * 64;
                b[0] = Aw[lt * 8 + lg];
                b[1] = Aw[(lt + 4) * 8 + lg];
#pragma unroll
                for (int s = 0; s < PSUB; s++) {
                    uint32_t a[4];
                    const int ab = lt * CH + toff - RS - 1 + base[s];
                    a[0] = B_sm[ab];
                    a[1] = B_sm[ab + 8];
                    a[2] = B_sm[ab + 4 * CH];
                    a[3] = B_sm[ab + 4 * CH + 8];
                    mma_f16(d[cls][s], a, b);
                }
            }
        }
        __syncthreads();
    }

    float bias_s[3];
    bias_s[0] = bias[0]; bias_s[1] = bias[1]; bias_s[2] = bias[2];
    float* outb = out + (size_t)img * 3 * HOUT * HOUT;
    if (lt < 2) {
#pragma unroll
        for (int cls = 0; cls < 4; cls++) {
            const int py = cls >> 1, px = cls & 1;
#pragma unroll
            for (int s = 0; s < PSUB; s++) {
#pragma unroll
                for (int rowh = 0; rowh < 2; rowh++) {
                    int p = warp * 64 + s * 16 + lg + 8 * rowh;
                    int q = q0 + (p >> 5), r = p & 31;
                    int oy = 2 * q + py, ox = 2 * r + px;
#pragma unroll
                    for (int cc = 0; cc < 2; cc++) {
                        int oc = 2 * lt + cc;
                        if (oc < 3) {
                            float v = d[cls][s][2 * rowh + cc] + bias_s[oc];
                            outb[((size_t)oc * HOUT + oy) * HOUT + ox] = v;
                        }
                    }
                }
            }
        }
    }
}

// ---------------- launch -----------------------------------------------------
extern "C" void kernel_launch(void* const* d_in, const int* in_sizes, int n_in,
                              void* d_out, int out_size) {
    const float* x  = (const float*)d_in[0];
    const float* gw = (const float*)d_in[1];
    const float* gb = (const float*)d_in[2];
    const float* z  = (const float*)d_in[3];
    const float* w1 = (const float*)d_in[4];
    const float* b1 = (const float*)d_in[5];
    const float* w2 = (const float*)d_in[6];
    const float* b2 = (const float*)d_in[7];
    const float* w3 = (const float*)d_in[8];
    const float* b3 = (const float*)d_in[9];
    float* out = (float*)d_out;

    float *lp;
    uint32_t *bf0, *bf1, *bf2, *wr1, *wr2, *wr3;
    cudaGetSymbolAddress((void**)&lp,  g_lp);
    cudaGetSymbolAddress((void**)&bf0, g_b0);
    cudaGetSymbolAddress((void**)&bf1, g_b1);
    cudaGetSymbolAddress((void**)&bf2, g_b2);
    cudaGetSymbolAddress((void**)&wr1, g_wr1);
    cudaGetSymbolAddress((void**)&wr2, g_wr2);
    cudaGetSymbolAddress((void**)&wr3, g_wr3);

    // smem sizes (bytes)
    const int SM1 = 2 * (4 * 8 * 136 + 2 * 8 * 168) * 4;   // 56320
    const int SM2 = 2 * (4 * 8 * 72 + 8 * 456) * 4;        // 47616
    const int SM3 = 2 * (1024 + 8 * 744) * 4;              // 55808

    cudaFuncSetAttribute(convt_h2<128, 8, 128, 4, 2, 136, 16, 168, true>,
                         cudaFuncAttributeMaxDynamicSharedMemorySize, SM1);
    cudaFuncSetAttribute(convt3_h2,
                         cudaFuncAttributeMaxDynamicSharedMemorySize, SM3);

    leaf_kernel<<<BATCH, 32>>>(x, gw, gb, lp);
    mix_kernel<<<dim3(16, BATCH / 8), 256>>>(lp, z, bf0);
    prep_all<<<848, 256>>>(w1, wr1, w2, wr2, w3, wr3);

    // conv1: 128->128, 8x8 -> 16x16, ReLU. MGRP=4, IMGB=2, MP=136, RS=16, CH=168
    convt_h2<128, 8, 128, 4, 2, 136, 16, 168, true>
        <<<dim3(4, BATCH / 2), 256, SM1>>>(bf0, wr1, b1, bf1);
    // conv2: 128->64, 16x16 -> 32x32, ReLU. MGRP=2, IMGB=1, MP=72, RS=24, CH=456
    convt_h2<128, 16, 64, 2, 1, 72, 24, 456, true>
        <<<dim3(4, BATCH), 256, SM2>>>(bf1, wr2, b2, bf2);
    // conv3: 64->3, 32x32 -> 64x64
    convt3_h2<<<dim3(2, BATCH), 256, SM3>>>(bf2, wr3, b3, out);
}

// round 10
// speedup vs baseline: 10.5893x; 1.3268x over previous
#include <cuda_runtime.h>
#include <cuda_fp16.h>
#include <math.h>
#include <stdint.h>

#define BATCH 512
#define LATENT 128

// ---------------- scratch (static device arrays; no runtime allocs) ----------
__device__ float    g_lp[BATCH * 32];
// pixel-major half2 buffers: [n][pix][ch-words]
__device__ uint32_t g_b0[BATCH * 64 * 64];        // [n][64 pix][64 w]
__device__ uint32_t g_b1[BATCH * 256 * 64];       // [n][256 pix][64 w]
__device__ uint32_t g_b2[BATCH * 1024 * 32];      // [n][1024 pix][32 w]
// k-contiguous weight rows: conv1/2 [cls][c][tap][m][8w], conv3 [c][ct16][oc8][8w]
__device__ uint32_t g_wr1[4 * 8 * 4 * 128 * 8];   // 131072
__device__ uint32_t g_wr2[4 * 8 * 4 * 64 * 8];    // 65536
__device__ uint32_t g_wr3[4 * 16 * 8 * 8];        // 4096

// ---------------- helpers ----------------
__device__ __forceinline__ uint32_t packh2(float lo, float hi) {
    __half2 h = __floats2half2_rn(lo, hi);
    return *(uint32_t*)&h;
}
__device__ __forceinline__ void mma_f16(float* d, const uint32_t* a, const uint32_t* b) {
    asm("mma.sync.aligned.m16n8k16.row.col.f32.f16.f16.f32 "
        "{%0,%1,%2,%3}, {%4,%5,%6,%7}, {%8,%9}, {%0,%1,%2,%3};"
        : "+f"(d[0]), "+f"(d[1]), "+f"(d[2]), "+f"(d[3])
        : "r"(a[0]), "r"(a[1]), "r"(a[2]), "r"(a[3]), "r"(b[0]), "r"(b[1]));
}
__device__ __forceinline__ void ldsm4(uint32_t* d, uint32_t addr) {
    asm volatile("ldmatrix.sync.aligned.m8n8.x4.shared.b16 {%0,%1,%2,%3}, [%4];"
                 : "=r"(d[0]), "=r"(d[1]), "=r"(d[2]), "=r"(d[3]) : "r"(addr));
}
__device__ __forceinline__ uint32_t smaddr(const void* p) {
    return (uint32_t)__cvta_generic_to_shared(p);
}
__device__ __forceinline__ void cp16(uint32_t* dst, const void* src) {
    uint32_t s = smaddr(dst);
    asm volatile("cp.async.ca.shared.global [%0], [%1], 16;" :: "r"(s), "l"(src) : "memory");
}
__device__ __forceinline__ void cp_commit() {
    asm volatile("cp.async.commit_group;" ::: "memory");
}
template <int N>
__device__ __forceinline__ void cp_wait() {
    asm volatile("cp.async.wait_group %0;" :: "n"(N) : "memory");
}

// ---------------- stage 1: gating + soft-tree leaf probabilities -------------
__global__ void leaf_kernel(const float* __restrict__ x,
                            const float* __restrict__ gw,
                            const float* __restrict__ gb,
                            float* __restrict__ lp) {
    int b = blockIdx.x;
    int lane = threadIdx.x;
    __shared__ float xs[LATENT];
    __shared__ float gs[32];
    for (int k = lane; k < LATENT; k += 32) xs[k] = x[b * LATENT + k];
    __syncthreads();
    if (lane < 31) {
        float acc = gb[lane];
#pragma unroll 8
        for (int k = 0; k < LATENT; k++) acc += xs[k] * gw[k * 31 + lane];
        gs[lane] = 1.0f / (1.0f + expf(-acc));
    }
    __syncthreads();
    float dens = 1.0f;
    int l = lane;
#pragma unroll
    for (int d = 1; d <= 5; d++) {
        int par  = l >> (6 - d);
        int gate = (1 << (d - 1)) - 1 + par;
        int bit  = (l >> (5 - d)) & 1;
        float gv = gs[gate];
        dens *= bit ? (1.0f - gv) : gv;
    }
    lp[b * 32 + l] = dens;
}

// ---------------- stage 2: mix, writes pixel-major half2 words ---------------
__global__ void mix_kernel(const float* __restrict__ lp,
                           const float* __restrict__ z,
                           uint32_t* __restrict__ out0) {
    __shared__ float lps[8][32];
    int tid = threadIdx.x;
    int idx = blockIdx.x * 256 + tid;          // [0, 4096)
    int b0 = blockIdx.y * 8;
    lps[tid >> 5][tid & 31] = lp[b0 * 32 + tid];
    __syncthreads();
    int icp = idx & 63, pix = idx >> 6;        // icp fastest -> coalesced writes
    const float4* z0 = (const float4*)(z + (size_t)(2 * icp * 64 + pix) * 32);
    const float4* z1 = (const float4*)(z + (size_t)((2 * icp + 1) * 64 + pix) * 32);
    float4 zr0[8], zr1[8];
#pragma unroll
    for (int j = 0; j < 8; j++) { zr0[j] = z0[j]; zr1[j] = z1[j]; }
#pragma unroll
    for (int bb = 0; bb < 8; bb++) {
        const float* lr = lps[bb];
        float a0 = 0.0f, a1 = 0.0f;
#pragma unroll
        for (int j = 0; j < 8; j++) {
            float4 u = zr0[j], v = zr1[j];
            a0 += u.x * lr[4 * j] + u.y * lr[4 * j + 1] + u.z * lr[4 * j + 2] + u.w * lr[4 * j + 3];
            a1 += v.x * lr[4 * j] + v.y * lr[4 * j + 1] + v.z * lr[4 * j + 2] + v.w * lr[4 * j + 3];
        }
        out0[(size_t)(b0 + bb) * 4096 + pix * 64 + icp] = packh2(a0, a1);
    }
}

// ---------------- merged weight prep -----------------------------------------
// conv1/2 layout: [cls][c][tap][m][kk8] ; kk = icp within chunk
template <int CIN, int COUT, int MSHIFT>
__device__ __forceinline__ void prep_common(const float* __restrict__ w,
                                            uint32_t* __restrict__ wr, int idx) {
    constexpr int M = 1 << MSHIFT;
    if (idx >= 4 * (CIN / 16) * 4 * M * 8) return;
    int kk   = idx & 7;
    int m    = (idx >> 3) & (M - 1);
    int rest = idx >> (3 + MSHIFT);
    int tap  = rest & 3;
    int c    = (rest >> 2) & 7;
    int cls  = rest >> 5;
    int py = cls >> 1, px = cls & 1;
    int ra = tap >> 1, rb = tap & 1;
    int ky = 3 - py - 2 * ra;
    int kx = 3 - px - 2 * rb;
    int ch = 2 * (c * 8 + kk);
    float v0 = 0.0f, v1 = 0.0f;
    if (m < COUT) {
        v0 = w[((size_t)ch * COUT + m) * 16 + ky * 4 + kx];
        v1 = w[((size_t)(ch + 1) * COUT + m) * 16 + ky * 4 + kx];
    }
    wr[idx] = packh2(v0, v1);
}

// conv3 layout: [c][ct = cls*4+tap][oc][kk8]
__global__ void prep_all(const float* __restrict__ w1, uint32_t* __restrict__ wr1,
                         const float* __restrict__ w2, uint32_t* __restrict__ wr2,
                         const float* __restrict__ w3, uint32_t* __restrict__ wr3) {
    int g = blockIdx.x;
    int tid = threadIdx.x;
    if (g < 512)      prep_common<128, 128, 7>(w1, wr1, g * 256 + tid);
    else if (g < 768) prep_common<128, 64, 6>(w2, wr2, (g - 512) * 256 + tid);
    else {
        int idx = (g - 768) * 256 + tid;
        if (idx >= 4096) return;
        int kk  = idx & 7;
        int oc  = (idx >> 3) & 7;
        int tap = (idx >> 6) & 3;
        int cls = (idx >> 8) & 3;
        int c   = idx >> 10;
        int py = cls >> 1, px = cls & 1;
        int ra = tap >> 1, rb = tap & 1;
        int ky = 3 - py - 2 * ra;
        int kx = 3 - px - 2 * rb;
        int ch = 2 * (c * 8 + kk);
        float v0 = 0.0f, v1 = 0.0f;
        if (oc < 3) {
            v0 = w3[((size_t)ch * 3 + oc) * 16 + ky * 4 + kx];
            v1 = w3[((size_t)(ch + 1) * 3 + oc) * 16 + ky * 4 + kx];
        }
        wr3[idx] = packh2(v0, v1);
    }
}

// ---------------- conv1/conv2: fp16 mma + ldmatrix, cp.async pipeline --------
// Smem: A rows [tap*M+m] of 8 words @ stride 12 (48B); B pixel slots of 8
// words @ stride 12, halo-padded grid PW x PW per image.
template <int CIN, int HIN, int COUT, int MGRP, int IMGB, bool RELU>
__launch_bounds__(256, 2)
__global__ void convt_h2(const uint32_t* __restrict__ in,
                         const uint32_t* __restrict__ wr,
                         const float* __restrict__ bias,
                         uint32_t* __restrict__ out) {
    constexpr int NPIX = HIN * HIN;
    constexpr int HOUT = 2 * HIN;
    constexpr int PW   = HIN + 2;
    constexpr int PPIX = PW * PW;
    constexpr int NGRP = 8 / MGRP;
    constexpr int NSUB = IMGB * NPIX / (8 * NGRP);
    constexpr int LOGH = (HIN == 8) ? 3 : 4;
    constexpr int M    = COUT;
    constexpr int ICPW = CIN / 2;
    constexpr int OCPW = COUT / 2;
    constexpr int NCH  = CIN / 16;
    constexpr int ASZ  = 4 * M * 12;
    constexpr int BSZ  = IMGB * PPIX * 12;

    extern __shared__ uint32_t smu[];
    uint32_t* Abuf[2] = { smu, smu + ASZ };
    uint32_t* Bbuf[2] = { smu + 2 * ASZ, smu + 2 * ASZ + BSZ };

    const int cls = blockIdx.x;
    const int img0 = blockIdx.y * IMGB;
    const int py = cls >> 1, px = cls & 1;
    const int tid = threadIdx.x;
    const int warp = tid >> 5, lane = tid & 31;
    const int lg = lane >> 2, lt = lane & 3;
    const int m0 = (warp % MGRP) * 32;
    const int n0 = (warp / MGRP) * (NSUB * 8);

    for (int i = tid; i < 2 * BSZ; i += 256) Bbuf[0][i] = 0;
    __syncthreads();

    // ldmatrix lane offsets (bytes)
    const uint32_t laneA = ((lane & 7) + 8 * ((lane >> 3) & 1)) * 48 + (lane >> 4) * 16;
    int toffB[4];
#pragma unroll
    for (int t = 0; t < 4; t++)
        toffB[t] = ((py - 1 + (t >> 1)) * PW + (px - 1 + (t & 1))) * 48;

    // per-x4-group B lane offsets: group s = 2j + (lane>>4), row pix n0+s*8+(lane&7)
    uint32_t bslot[NSUB / 2];
#pragma unroll
    for (int j = 0; j < NSUB / 2; j++) {
        int s = 2 * j + (lane >> 4);
        int n = n0 + s * 8 + (lane & 7);
        int im = n >> (2 * LOGH);
        int pix = n & (NPIX - 1);
        int q = pix >> LOGH, r = pix & (HIN - 1);
        bslot[j] = (im * PPIX + (q + 1) * PW + (r + 1)) * 48 + ((lane >> 3) & 1) * 16;
    }

    float d[2][NSUB][4];
#pragma unroll
    for (int mm = 0; mm < 2; mm++)
#pragma unroll
        for (int s = 0; s < NSUB; s++)
#pragma unroll
            for (int j = 0; j < 4; j++) d[mm][s][j] = 0.0f;

    const uint32_t* wrc = wr + (size_t)cls * NCH * 4 * M * 8;

    auto prefetch = [&](int c) {
        uint32_t* A = Abuf[c & 1];
        uint32_t* B = Bbuf[c & 1];
        // A: 4*M rows x 2 halves
        for (int idx = tid; idx < 4 * M * 2; idx += 256) {
            int row = idx >> 1, part = idx & 1;
            cp16(A + row * 12 + part * 4, wrc + c * (4 * M * 8) + row * 8 + part * 4);
        }
        // B: interior pixels, 2 halves each
        for (int idx = tid; idx < IMGB * NPIX * 2; idx += 256) {
            int part = idx & 1;
            int rest = idx >> 1;
            int pix = rest & (NPIX - 1);
            int im  = rest >> (2 * LOGH);
            int q = pix >> LOGH, r = pix & (HIN - 1);
            cp16(B + (im * PPIX + (q + 1) * PW + (r + 1)) * 12 + part * 4,
                 in + ((size_t)(img0 + im) * NPIX + pix) * ICPW + c * 8 + part * 4);
        }
    };

    prefetch(0);
    cp_commit();

    for (int c = 0; c < NCH; c++) {
        if (c + 1 < NCH) { prefetch(c + 1); cp_commit(); cp_wait<1>(); }
        else             { cp_wait<0>(); }
        __syncthreads();
        const uint32_t ab = smaddr(Abuf[c & 1]);
        const uint32_t bb = smaddr(Bbuf[c & 1]);

#pragma unroll
        for (int t = 0; t < 4; t++) {
            uint32_t a[2][4];
            ldsm4(a[0], ab + (t * M + m0) * 48 + laneA);
            ldsm4(a[1], ab + (t * M + m0 + 16) * 48 + laneA);
            const int tb = toffB[t];
#pragma unroll
            for (int j = 0; j < NSUB / 2; j++) {
                uint32_t bf[4];
                ldsm4(bf, bb + bslot[j] + tb);
                mma_f16(d[0][2 * j],     a[0], bf + 0);
                mma_f16(d[1][2 * j],     a[1], bf + 0);
                mma_f16(d[0][2 * j + 1], a[0], bf + 2);
                mma_f16(d[1][2 * j + 1], a[1], bf + 2);
            }
        }
        __syncthreads();
    }

    // epilogue: bias(+ReLU), shfl pair-exchange, pixel-major packed writes
    float bv[2][2];
#pragma unroll
    for (int mm = 0; mm < 2; mm++) {
        bv[mm][0] = bias[m0 + mm * 16 + lg];
        bv[mm][1] = bias[m0 + mm * 16 + lg + 8];
    }
#pragma unroll
    for (int mm = 0; mm < 2; mm++) {
#pragma unroll
        for (int s = 0; s < NSUB; s++) {
            int nb = n0 + s * 8 + 2 * lt;
            int im = nb >> (2 * LOGH);
            int pix = nb & (NPIX - 1);
            int q = pix >> LOGH, r = pix & (HIN - 1);
            int op0 = (2 * q + py) * HOUT + 2 * r + px;
            uint32_t* outw = out + (size_t)(img0 + im) * HOUT * HOUT * OCPW;
#pragma unroll
            for (int half = 0; half < 2; half++) {
                int oc = m0 + mm * 16 + lg + 8 * half;
                float v0 = d[mm][s][2 * half]     + bv[mm][half];
                float v1 = d[mm][s][2 * half + 1] + bv[mm][half];
                if (RELU) { v0 = fmaxf(v0, 0.0f); v1 = fmaxf(v1, 0.0f); }
                float p0 = __shfl_down_sync(0xffffffffu, v0, 4);
                float p1 = __shfl_down_sync(0xffffffffu, v1, 4);
                if (!(lg & 1)) {
                    int ocp = oc >> 1;
                    outw[(size_t)op0 * OCPW + ocp]       = packh2(v0, p0);
                    outw[(size_t)(op0 + 2) * OCPW + ocp] = packh2(v1, p1);
                }
            }
        }
    }
}

// ---------------- conv3: fused classes, swapped roles, ldmatrix --------------
__launch_bounds__(256, 2)
__global__ void convt3_h2(const uint32_t* __restrict__ in,
                          const uint32_t* __restrict__ wr,
                          const float* __restrict__ bias,
                          float* __restrict__ out) {
    constexpr int HIN = 32, HOUT = 64;
    constexpr int PW = HIN + 2;               // 34
    constexpr int ROWS = 18;
    constexpr int PSUB = 4;
    constexpr int WSZ = 16 * 8 * 12;          // 1536 words (16 ct x 8 oc rows)
    constexpr int BSZ = ROWS * PW * 12;       // 7344 words (612 pixel slots)

    extern __shared__ uint32_t smu[];
    uint32_t* Wbuf[2] = { smu, smu + WSZ };
    uint32_t* Bbuf[2] = { smu + 2 * WSZ, smu + 2 * WSZ + BSZ };

    const int q0 = blockIdx.x * 16;
    const int img = blockIdx.y;
    const int tid = threadIdx.x;
    const int warp = tid >> 5, lane = tid & 31;
    const int lg = lane >> 2, lt = lane & 3;

    for (int i = tid; i < 2 * BSZ; i += 256) Bbuf[0][i] = 0;
    __syncthreads();

    // weight ldmatrix lane offset: ct = ct0 + (lane>>4), row oc = lane&7
    const uint32_t laneW = (lane >> 4) * (8 * 48) + (lane & 7) * 48 + ((lane >> 3) & 1) * 16;
    // pixel (A-operand) lane offsets per subtile
    uint32_t aslot[PSUB];
#pragma unroll
    for (int s = 0; s < PSUB; s++) {
        int p = warp * 64 + s * 16;
        int ql = p >> 5, r0 = p & 31;
        aslot[s] = ((ql + 1) * PW + r0 + 1 + (lane & 7) + 8 * ((lane >> 3) & 1)) * 48
                 + (lane >> 4) * 16;
    }

    float d[4][PSUB][4];
#pragma unroll
    for (int c = 0; c < 4; c++)
#pragma unroll
        for (int s = 0; s < PSUB; s++)
#pragma unroll
            for (int j = 0; j < 4; j++) d[c][s][j] = 0.0f;

    auto prefetch = [&](int c) {
        uint32_t* W = Wbuf[c & 1];
        uint32_t* B = Bbuf[c & 1];
        // weights: 128 rows x 2 halves
        for (int idx = tid; idx < 256; idx += 256) {
            int row = idx >> 1, part = idx & 1;
            cp16(W + row * 12 + part * 4, wr + c * 1024 + row * 8 + part * 4);
        }
        // image rows q0-1 .. q0+16, 32 cols, 2 halves
        for (int idx = tid; idx < ROWS * 32 * 2; idx += 256) {
            int part = idx & 1;
            int rest = idx >> 1;
            int col = rest & 31;
            int rr  = rest >> 5;
            int row = q0 - 1 + rr;
            if (row >= 0 && row < HIN)
                cp16(B + (rr * PW + col + 1) * 12 + part * 4,
                     in + ((size_t)img * 1024 + row * 32 + col) * 32 + c * 8 + part * 4);
        }
    };

    prefetch(0);
    cp_commit();

    for (int c = 0; c < 4; c++) {
        if (c + 1 < 4) { prefetch(c + 1); cp_commit(); cp_wait<1>(); }
        else           { cp_wait<0>(); }
        __syncthreads();
        const uint32_t wb = smaddr(Wbuf[c & 1]);
        const uint32_t bb = smaddr(Bbuf[c & 1]);

#pragma unroll
        for (int cls = 0; cls < 4; cls++) {
            const int py = cls >> 1, px = cls & 1;
#pragma unroll
            for (int tp = 0; tp < 2; tp++) {
                uint32_t wf[4];
                ldsm4(wf, wb + (cls * 4 + 2 * tp) * (8 * 48) + laneW);
#pragma unroll
                for (int t2 = 0; t2 < 2; t2++) {
                    const int t = 2 * tp + t2;
                    const int ra = t >> 1, rb = t & 1;
                    const int sh = ((py - 1 + ra) * PW + (px - 1 + rb)) * 48;
#pragma unroll
                    for (int s = 0; s < PSUB; s++) {
                        uint32_t af[4];
                        ldsm4(af, bb + aslot[s] + sh);
                        mma_f16(d[cls][s], af, wf + 2 * t2);
                    }
                }
            }
        }
        __syncthreads();
    }

    float bias_s[3];
    bias_s[0] = bias[0]; bias_s[1] = bias[1]; bias_s[2] = bias[2];
    float* outb = out + (size_t)img * 3 * HOUT * HOUT;
    if (lt < 2) {
#pragma unroll
        for (int cls = 0; cls < 4; cls++) {
            const int py = cls >> 1, px = cls & 1;
#pragma unroll
            for (int s = 0; s < PSUB; s++) {
#pragma unroll
                for (int rowh = 0; rowh < 2; rowh++) {
                    int p = warp * 64 + s * 16 + lg + 8 * rowh;
                    int q = q0 + (p >> 5), r = p & 31;
                    int oy = 2 * q + py, ox = 2 * r + px;
#pragma unroll
                    for (int cc = 0; cc < 2; cc++) {
                        int oc = 2 * lt + cc;
                        if (oc < 3) {
                            float v = d[cls][s][2 * rowh + cc] + bias_s[oc];
                            outb[((size_t)oc * HOUT + oy) * HOUT + ox] = v;
                        }
                    }
                }
            }
        }
    }
}

// ---------------- launch -----------------------------------------------------
extern "C" void kernel_launch(void* const* d_in, const int* in_sizes, int n_in,
                              void* d_out, int out_size) {
    const float* x  = (const float*)d_in[0];
    const float* gw = (const float*)d_in[1];
    const float* gb = (const float*)d_in[2];
    const float* z  = (const float*)d_in[3];
    const float* w1 = (const float*)d_in[4];
    const float* b1 = (const float*)d_in[5];
    const float* w2 = (const float*)d_in[6];
    const float* b2 = (const float*)d_in[7];
    const float* w3 = (const float*)d_in[8];
    const float* b3 = (const float*)d_in[9];
    float* out = (float*)d_out;

    float *lp;
    uint32_t *bf0, *bf1, *bf2, *wr1, *wr2, *wr3;
    cudaGetSymbolAddress((void**)&lp,  g_lp);
    cudaGetSymbolAddress((void**)&bf0, g_b0);
    cudaGetSymbolAddress((void**)&bf1, g_b1);
    cudaGetSymbolAddress((void**)&bf2, g_b2);
    cudaGetSymbolAddress((void**)&wr1, g_wr1);
    cudaGetSymbolAddress((void**)&wr2, g_wr2);
    cudaGetSymbolAddress((void**)&wr3, g_wr3);

    // smem (bytes): (ASZ + BSZ) * 2 buffers * 4
    const int SM1 = (4 * 128 * 12 + 2 * 100 * 12) * 2 * 4;   // 68352
    const int SM2 = (4 * 64 * 12 + 324 * 12) * 2 * 4;        // 55680
    const int SM3 = (16 * 8 * 12 + 18 * 34 * 12) * 2 * 4;    // 71040

    cudaFuncSetAttribute(convt_h2<128, 8, 128, 4, 2, true>,
                         cudaFuncAttributeMaxDynamicSharedMemorySize, SM1);
    cudaFuncSetAttribute(convt_h2<128, 16, 64, 2, 1, true>,
                         cudaFuncAttributeMaxDynamicSharedMemorySize, SM2);
    cudaFuncSetAttribute(convt3_h2,
                         cudaFuncAttributeMaxDynamicSharedMemorySize, SM3);

    leaf_kernel<<<BATCH, 32>>>(x, gw, gb, lp);
    mix_kernel<<<dim3(16, BATCH / 8), 256>>>(lp, z, bf0);
    prep_all<<<784, 256>>>(w1, wr1, w2, wr2, w3, wr3);

    // conv1: 128->128, 8x8 -> 16x16, ReLU. MGRP=4, IMGB=2
    convt_h2<128, 8, 128, 4, 2, true>
        <<<dim3(4, BATCH / 2), 256, SM1>>>(bf0, wr1, b1, bf1);
    // conv2: 128->64, 16x16 -> 32x32, ReLU. MGRP=2, IMGB=1
    convt_h2<128, 16, 64, 2, 1, true>
        <<<dim3(4, BATCH), 256, SM2>>>(bf1, wr2, b2, bf2);
    // conv3: 64->3, 32x32 -> 64x64
    convt3_h2<<<dim3(2, BATCH), 256, SM3>>>(bf2, wr3, b3, out);
}

// round 11
// speedup vs baseline: 11.8270x; 1.1169x over previous
#include <cuda_runtime.h>
#include <cuda_fp16.h>
#include <math.h>
#include <stdint.h>

#define BATCH 512
#define LATENT 128

// ---------------- scratch (static device arrays; no runtime allocs) ----------
__device__ float    g_lp[BATCH * 32];
// pixel-major half2 buffers: [n][pix][ch-words]
__device__ uint32_t g_b0[BATCH * 64 * 64];
__device__ uint32_t g_b1[BATCH * 256 * 64];
__device__ uint32_t g_b2[BATCH * 1024 * 32];
// per-lane A-fragment weights: conv1/2 [cls][c][tap][mt][lane][4w], conv3 [c][cls][tap][lane][2w]
__device__ uint32_t g_wr1[4 * 8 * 4 * 8 * 32 * 4];   // 131072
__device__ uint32_t g_wr2[4 * 8 * 4 * 4 * 32 * 4];   // 65536
__device__ uint32_t g_wr3[4 * 4 * 4 * 32 * 2];       // 4096

// ---------------- helpers ----------------
__device__ __forceinline__ uint32_t packh2(float lo, float hi) {
    __half2 h = __floats2half2_rn(lo, hi);
    return *(uint32_t*)&h;
}
__device__ __forceinline__ void mma_f16(float* d, const uint32_t* a, const uint32_t* b) {
    asm("mma.sync.aligned.m16n8k16.row.col.f32.f16.f16.f32 "
        "{%0,%1,%2,%3}, {%4,%5,%6,%7}, {%8,%9}, {%0,%1,%2,%3};"
        : "+f"(d[0]), "+f"(d[1]), "+f"(d[2]), "+f"(d[3])
        : "r"(a[0]), "r"(a[1]), "r"(a[2]), "r"(a[3]), "r"(b[0]), "r"(b[1]));
}
__device__ __forceinline__ void ldsm4(uint32_t* d, uint32_t addr) {
    asm volatile("ldmatrix.sync.aligned.m8n8.x4.shared.b16 {%0,%1,%2,%3}, [%4];"
                 : "=r"(d[0]), "=r"(d[1]), "=r"(d[2]), "=r"(d[3]) : "r"(addr));
}
__device__ __forceinline__ uint32_t smaddr(const void* p) {
    return (uint32_t)__cvta_generic_to_shared(p);
}
__device__ __forceinline__ void cp16(uint32_t* dst, const void* src) {
    uint32_t s = smaddr(dst);
    asm volatile("cp.async.ca.shared.global [%0], [%1], 16;" :: "r"(s), "l"(src) : "memory");
}
__device__ __forceinline__ void cp_commit() {
    asm volatile("cp.async.commit_group;" ::: "memory");
}
template <int N>
__device__ __forceinline__ void cp_wait() {
    asm volatile("cp.async.wait_group %0;" :: "n"(N) : "memory");
}

// ---------------- stage 1: gating + soft-tree leaf probabilities -------------
__global__ void leaf_kernel(const float* __restrict__ x,
                            const float* __restrict__ gw,
                            const float* __restrict__ gb,
                            float* __restrict__ lp) {
    int b = blockIdx.x;
    int lane = threadIdx.x;
    __shared__ float xs[LATENT];
    __shared__ float gs[32];
    for (int k = lane; k < LATENT; k += 32) xs[k] = x[b * LATENT + k];
    __syncthreads();
    if (lane < 31) {
        float acc = gb[lane];
#pragma unroll 8
        for (int k = 0; k < LATENT; k++) acc += xs[k] * gw[k * 31 + lane];
        gs[lane] = 1.0f / (1.0f + expf(-acc));
    }
    __syncthreads();
    float dens = 1.0f;
    int l = lane;
#pragma unroll
    for (int d = 1; d <= 5; d++) {
        int par  = l >> (6 - d);
        int gate = (1 << (d - 1)) - 1 + par;
        int bit  = (l >> (5 - d)) & 1;
        float gv = gs[gate];
        dens *= bit ? (1.0f - gv) : gv;
    }
    lp[b * 32 + l] = dens;
}

// ---------------- stage 2: mix, writes pixel-major half2 words ---------------
__global__ void mix_kernel(const float* __restrict__ lp,
                           const float* __restrict__ z,
                           uint32_t* __restrict__ out0) {
    __shared__ float lps[8][32];
    int tid = threadIdx.x;
    int idx = blockIdx.x * 256 + tid;
    int b0 = blockIdx.y * 8;
    lps[tid >> 5][tid & 31] = lp[b0 * 32 + tid];
    __syncthreads();
    int icp = idx & 63, pix = idx >> 6;
    const float4* z0 = (const float4*)(z + (size_t)(2 * icp * 64 + pix) * 32);
    const float4* z1 = (const float4*)(z + (size_t)((2 * icp + 1) * 64 + pix) * 32);
    float4 zr0[8], zr1[8];
#pragma unroll
    for (int j = 0; j < 8; j++) { zr0[j] = z0[j]; zr1[j] = z1[j]; }
#pragma unroll
    for (int bb = 0; bb < 8; bb++) {
        const float* lr = lps[bb];
        float a0 = 0.0f, a1 = 0.0f;
#pragma unroll
        for (int j = 0; j < 8; j++) {
            float4 u = zr0[j], v = zr1[j];
            a0 += u.x * lr[4 * j] + u.y * lr[4 * j + 1] + u.z * lr[4 * j + 2] + u.w * lr[4 * j + 3];
            a1 += v.x * lr[4 * j] + v.y * lr[4 * j + 1] + v.z * lr[4 * j + 2] + v.w * lr[4 * j + 3];
        }
        out0[(size_t)(b0 + bb) * 4096 + pix * 64 + icp] = packh2(a0, a1);
    }
}

// ---------------- merged weight prep: per-lane mma A-fragments ---------------
// conv1/2 out: [cls][c][tap][mt][lane][j4]; element (m, kk) with
//   m = mt*16 + lg + 8*(j&1), kk = lt + 4*(j>>1)  (lg=lane>>2, lt=lane&3)
template <int COUT, int MSHIFT>
__device__ __forceinline__ void prep_frag(const float* __restrict__ w,
                                          uint32_t* __restrict__ wr, int idx) {
    constexpr int MT = 1 << MSHIFT;
    if (idx >= 4 * 8 * 4 * MT * 32 * 4) return;
    int j    = idx & 3;
    int lane = (idx >> 2) & 31;
    int mt   = (idx >> 7) & (MT - 1);
    int t    = (idx >> (7 + MSHIFT)) & 3;
    int c    = (idx >> (9 + MSHIFT)) & 7;
    int cls  = idx >> (12 + MSHIFT);
    int lg = lane >> 2, lt = lane & 3;
    int m  = mt * 16 + lg + 8 * (j & 1);
    int kk = lt + 4 * (j >> 1);
    int py = cls >> 1, px = cls & 1;
    int ra = t >> 1, rb = t & 1;
    int ky = 3 - py - 2 * ra;
    int kx = 3 - px - 2 * rb;
    int ch = 2 * (c * 8 + kk);
    float v0 = w[((size_t)ch * COUT + m) * 16 + ky * 4 + kx];
    float v1 = w[((size_t)(ch + 1) * COUT + m) * 16 + ky * 4 + kx];
    wr[idx] = packh2(v0, v1);
}

// conv3 out: [c][cls][tap][lane][j2]; element (kk = lt+4*j, oc = lg)
__global__ void prep_all(const float* __restrict__ w1, uint32_t* __restrict__ wr1,
                         const float* __restrict__ w2, uint32_t* __restrict__ wr2,
                         const float* __restrict__ w3, uint32_t* __restrict__ wr3) {
    int g = blockIdx.x;
    int tid = threadIdx.x;
    if (g < 512)      prep_frag<128, 3>(w1, wr1, g * 256 + tid);
    else if (g < 768) prep_frag<64, 2>(w2, wr2, (g - 512) * 256 + tid);
    else {
        int idx = (g - 768) * 256 + tid;
        if (idx >= 4096) return;
        int j    = idx & 1;
        int lane = (idx >> 1) & 31;
        int t    = (idx >> 6) & 3;
        int cls  = (idx >> 8) & 3;
        int c    = idx >> 10;
        int lg = lane >> 2, lt = lane & 3;
        int kk = lt + 4 * j;
        int oc = lg;
        int py = cls >> 1, px = cls & 1;
        int ra = t >> 1, rb = t & 1;
        int ky = 3 - py - 2 * ra;
        int kx = 3 - px - 2 * rb;
        int ch = 2 * (c * 8 + kk);
        float v0 = 0.0f, v1 = 0.0f;
        if (oc < 3) {
            v0 = w3[((size_t)ch * 3 + oc) * 16 + ky * 4 + kx];
            v1 = w3[((size_t)(ch + 1) * 3 + oc) * 16 + ky * 4 + kx];
        }
        wr3[idx] = packh2(v0, v1);
    }
}

// ---------------- conv1/conv2: fp16 mma, A by LDG.128, B by ldmatrix ---------
template <int CIN, int HIN, int COUT, int MGRP, int IMGB, bool RELU>
__launch_bounds__(256, 2)
__global__ void convt_h2(const uint32_t* __restrict__ in,
                         const uint32_t* __restrict__ wr,
                         const float* __restrict__ bias,
                         uint32_t* __restrict__ out) {
    constexpr int NPIX = HIN * HIN;
    constexpr int HOUT = 2 * HIN;
    constexpr int PW   = HIN + 2;
    constexpr int PPIX = PW * PW;
    constexpr int NGRP = 8 / MGRP;
    constexpr int NSUB = IMGB * NPIX / (8 * NGRP);
    constexpr int LOGH = (HIN == 8) ? 3 : 4;
    constexpr int MT   = COUT / 16;
    constexpr int ICPW = CIN / 2;
    constexpr int OCPW = COUT / 2;
    constexpr int NCH  = CIN / 16;
    constexpr int BSZ  = IMGB * PPIX * 12;

    extern __shared__ uint32_t smu[];
    uint32_t* Bbuf[2] = { smu, smu + BSZ };

    const int cls = blockIdx.x;
    const int img0 = blockIdx.y * IMGB;
    const int py = cls >> 1, px = cls & 1;
    const int tid = threadIdx.x;
    const int warp = tid >> 5, lane = tid & 31;
    const int lg = lane >> 2, lt = lane & 3;
    const int m0 = (warp % MGRP) * 32;
    const int n0 = (warp / MGRP) * (NSUB * 8);

    for (int i = tid; i < 2 * BSZ; i += 256) Bbuf[0][i] = 0;
    __syncthreads();

    int toffB[4];
#pragma unroll
    for (int t = 0; t < 4; t++)
        toffB[t] = ((py - 1 + (t >> 1)) * PW + (px - 1 + (t & 1))) * 48;

    uint32_t bslot[NSUB / 2];
#pragma unroll
    for (int j = 0; j < NSUB / 2; j++) {
        int s = 2 * j + (lane >> 4);
        int n = n0 + s * 8 + (lane & 7);
        int im = n >> (2 * LOGH);
        int pix = n & (NPIX - 1);
        int q = pix >> LOGH, r = pix & (HIN - 1);
        bslot[j] = (im * PPIX + (q + 1) * PW + (r + 1)) * 48 + ((lane >> 3) & 1) * 16;
    }

    float d[2][NSUB][4];
#pragma unroll
    for (int mm = 0; mm < 2; mm++)
#pragma unroll
        for (int s = 0; s < NSUB; s++)
#pragma unroll
            for (int j = 0; j < 4; j++) d[mm][s][j] = 0.0f;

    // A fragment base: [cls][c][tap][mt][lane][4]
    const uint32_t* wA = wr + ((size_t)cls * NCH * 4 * MT + (m0 >> 4)) * 128 + lane * 4;

    auto prefetchB = [&](int c) {
        uint32_t* B = Bbuf[c & 1];
        for (int idx = tid; idx < IMGB * NPIX * 2; idx += 256) {
            int part = idx & 1;
            int rest = idx >> 1;
            int pix = rest & (NPIX - 1);
            int im  = rest >> (2 * LOGH);
            int q = pix >> LOGH, r = pix & (HIN - 1);
            cp16(B + (im * PPIX + (q + 1) * PW + (r + 1)) * 12 + part * 4,
                 in + ((size_t)(img0 + im) * NPIX + pix) * ICPW + c * 8 + part * 4);
        }
    };

    prefetchB(0);
    cp_commit();

    for (int c = 0; c < NCH; c++) {
        // A fragments for all 4 taps via coalesced LDG.128 (overlaps staging)
        uint4 a4[4][2];
#pragma unroll
        for (int t = 0; t < 4; t++)
#pragma unroll
            for (int mm = 0; mm < 2; mm++)
                a4[t][mm] = *(const uint4*)(wA + ((size_t)(c * 4 + t) * MT + mm) * 128);

        if (c + 1 < NCH) { prefetchB(c + 1); cp_commit(); cp_wait<1>(); }
        else             { cp_wait<0>(); }
        __syncthreads();
        const uint32_t bb = smaddr(Bbuf[c & 1]);

#pragma unroll
        for (int t = 0; t < 4; t++) {
            const int tb = toffB[t];
#pragma unroll
            for (int j = 0; j < NSUB / 2; j++) {
                uint32_t bf[4];
                ldsm4(bf, bb + bslot[j] + tb);
                mma_f16(d[0][2 * j],     (const uint32_t*)&a4[t][0], bf + 0);
                mma_f16(d[1][2 * j],     (const uint32_t*)&a4[t][1], bf + 0);
                mma_f16(d[0][2 * j + 1], (const uint32_t*)&a4[t][0], bf + 2);
                mma_f16(d[1][2 * j + 1], (const uint32_t*)&a4[t][1], bf + 2);
            }
        }
        __syncthreads();
    }

    // epilogue: bias(+ReLU), shfl pair-exchange, pixel-major packed writes
    float bv[2][2];
#pragma unroll
    for (int mm = 0; mm < 2; mm++) {
        bv[mm][0] = bias[m0 + mm * 16 + lg];
        bv[mm][1] = bias[m0 + mm * 16 + lg + 8];
    }
#pragma unroll
    for (int mm = 0; mm < 2; mm++) {
#pragma unroll
        for (int s = 0; s < NSUB; s++) {
            int nb = n0 + s * 8 + 2 * lt;
            int im = nb >> (2 * LOGH);
            int pix = nb & (NPIX - 1);
            int q = pix >> LOGH, r = pix & (HIN - 1);
            int op0 = (2 * q + py) * HOUT + 2 * r + px;
            uint32_t* outw = out + (size_t)(img0 + im) * HOUT * HOUT * OCPW;
#pragma unroll
            for (int half = 0; half < 2; half++) {
                int oc = m0 + mm * 16 + lg + 8 * half;
                float v0 = d[mm][s][2 * half]     + bv[mm][half];
                float v1 = d[mm][s][2 * half + 1] + bv[mm][half];
                if (RELU) { v0 = fmaxf(v0, 0.0f); v1 = fmaxf(v1, 0.0f); }
                float p0 = __shfl_down_sync(0xffffffffu, v0, 4);
                float p1 = __shfl_down_sync(0xffffffffu, v1, 4);
                if (!(lg & 1)) {
                    int ocp = oc >> 1;
                    outw[(size_t)op0 * OCPW + ocp]       = packh2(v0, p0);
                    outw[(size_t)(op0 + 2) * OCPW + ocp] = packh2(v1, p1);
                }
            }
        }
    }
}

// ---------------- conv3: fused classes, swapped roles, weights by LDG --------
__launch_bounds__(256, 2)
__global__ void convt3_h2(const uint32_t* __restrict__ in,
                          const uint32_t* __restrict__ wr,
                          const float* __restrict__ bias,
                          float* __restrict__ out) {
    constexpr int HIN = 32, HOUT = 64;
    constexpr int PW = HIN + 2;
    constexpr int ROWS = 18;
    constexpr int PSUB = 4;
    constexpr int BSZ = ROWS * PW * 12;       // 7344 words

    extern __shared__ uint32_t smu[];
    uint32_t* Bbuf[2] = { smu, smu + BSZ };

    const int q0 = blockIdx.x * 16;
    const int img = blockIdx.y;
    const int tid = threadIdx.x;
    const int warp = tid >> 5, lane = tid & 31;
    const int lg = lane >> 2, lt = lane & 3;

    for (int i = tid; i < 2 * BSZ; i += 256) Bbuf[0][i] = 0;
    __syncthreads();

    uint32_t aslot[PSUB];
#pragma unroll
    for (int s = 0; s < PSUB; s++) {
        int p = warp * 64 + s * 16;
        int ql = p >> 5, r0 = p & 31;
        aslot[s] = ((ql + 1) * PW + r0 + 1 + (lane & 7) + 8 * ((lane >> 3) & 1)) * 48
                 + (lane >> 4) * 16;
    }

    float d[4][PSUB][4];
#pragma unroll
    for (int c = 0; c < 4; c++)
#pragma unroll
        for (int s = 0; s < PSUB; s++)
#pragma unroll
            for (int j = 0; j < 4; j++) d[c][s][j] = 0.0f;

    auto prefetchB = [&](int c) {
        uint32_t* B = Bbuf[c & 1];
        for (int idx = tid; idx < ROWS * 32 * 2; idx += 256) {
            int part = idx & 1;
            int rest = idx >> 1;
            int col = rest & 31;
            int rr  = rest >> 5;
            int row = q0 - 1 + rr;
            if (row >= 0 && row < HIN)
                cp16(B + (rr * PW + col + 1) * 12 + part * 4,
                     in + ((size_t)img * 1024 + row * 32 + col) * 32 + c * 8 + part * 4);
        }
    };

    prefetchB(0);
    cp_commit();

    for (int c = 0; c < 4; c++) {
        if (c + 1 < 4) { prefetchB(c + 1); cp_commit(); cp_wait<1>(); }
        else           { cp_wait<0>(); }
        __syncthreads();
        const uint32_t bb = smaddr(Bbuf[c & 1]);

#pragma unroll
        for (int cls = 0; cls < 4; cls++) {
            const int py = cls >> 1, px = cls & 1;
            // weight fragments for all 4 taps (L1-resident, 4KB total)
            uint2 wv[4];
#pragma unroll
            for (int t = 0; t < 4; t++)
                wv[t] = *(const uint2*)(wr + (((c * 4 + cls) * 4 + t) * 32 + lane) * 2);
#pragma unroll
            for (int t = 0; t < 4; t++) {
                const int ra = t >> 1, rb = t & 1;
                const int sh = ((py - 1 + ra) * PW + (px - 1 + rb)) * 48;
                uint32_t b[2] = { wv[t].x, wv[t].y };
#pragma unroll
                for (int s = 0; s < PSUB; s++) {
                    uint32_t af[4];
                    ldsm4(af, bb + aslot[s] + sh);
                    mma_f16(d[cls][s], af, b);
                }
            }
        }
        __syncthreads();
    }

    float bias_s[3];
    bias_s[0] = bias[0]; bias_s[1] = bias[1]; bias_s[2] = bias[2];
    float* outb = out + (size_t)img * 3 * HOUT * HOUT;
    if (lt < 2) {
#pragma unroll
        for (int cls = 0; cls < 4; cls++) {
            const int py = cls >> 1, px = cls & 1;
#pragma unroll
            for (int s = 0; s < PSUB; s++) {
#pragma unroll
                for (int rowh = 0; rowh < 2; rowh++) {
                    int p = warp * 64 + s * 16 + lg + 8 * rowh;
                    int q = q0 + (p >> 5), r = p & 31;
                    int oy = 2 * q + py, ox = 2 * r + px;
#pragma unroll
                    for (int cc = 0; cc < 2; cc++) {
                        int oc = 2 * lt + cc;
                        if (oc < 3) {
                            float v = d[cls][s][2 * rowh + cc] + bias_s[oc];
                            outb[((size_t)oc * HOUT + oy) * HOUT + ox] = v;
                        }
                    }
                }
            }
        }
    }
}

// ---------------- launch -----------------------------------------------------
extern "C" void kernel_launch(void* const* d_in, const int* in_sizes, int n_in,
                              void* d_out, int out_size) {
    const float* x  = (const float*)d_in[0];
    const float* gw = (const float*)d_in[1];
    const float* gb = (const float*)d_in[2];
    const float* z  = (const float*)d_in[3];
    const float* w1 = (const float*)d_in[4];
    const float* b1 = (const float*)d_in[5];
    const float* w2 = (const float*)d_in[6];
    const float* b2 = (const float*)d_in[7];
    const float* w3 = (const float*)d_in[8];
    const float* b3 = (const float*)d_in[9];
    float* out = (float*)d_out;

    float *lp;
    uint32_t *bf0, *bf1, *bf2, *wr1, *wr2, *wr3;
    cudaGetSymbolAddress((void**)&lp,  g_lp);
    cudaGetSymbolAddress((void**)&bf0, g_b0);
    cudaGetSymbolAddress((void**)&bf1, g_b1);
    cudaGetSymbolAddress((void**)&bf2, g_b2);
    cudaGetSymbolAddress((void**)&wr1, g_wr1);
    cudaGetSymbolAddress((void**)&wr2, g_wr2);
    cudaGetSymbolAddress((void**)&wr3, g_wr3);

    // smem (bytes): B double buffer only
    const int SM1 = 2 * (2 * 100 * 12) * 4;   // 19200
    const int SM2 = 2 * (324 * 12) * 4;       // 31104
    const int SM3 = 2 * (18 * 34 * 12) * 4;   // 58752

    cudaFuncSetAttribute(convt3_h2,
                         cudaFuncAttributeMaxDynamicSharedMemorySize, SM3);

    leaf_kernel<<<BATCH, 32>>>(x, gw, gb, lp);
    mix_kernel<<<dim3(16, BATCH / 8), 256>>>(lp, z, bf0);
    prep_all<<<784, 256>>>(w1, wr1, w2, wr2, w3, wr3);

    // conv1: 128->128, 8x8 -> 16x16, ReLU. MGRP=4, IMGB=2
    convt_h2<128, 8, 128, 4, 2, true>
        <<<dim3(4, BATCH / 2), 256, SM1>>>(bf0, wr1, b1, bf1);
    // conv2: 128->64, 16x16 -> 32x32, ReLU. MGRP=2, IMGB=1
    convt_h2<128, 16, 64, 2, 1, true>
        <<<dim3(4, BATCH), 256, SM2>>>(bf1, wr2, b2, bf2);
    // conv3: 64->3, 32x32 -> 64x64
    convt3_h2<<<dim3(2, BATCH), 256, SM3>>>(bf2, wr3, b3, out);
}